// round 2
// baseline (speedup 1.0000x reference)
#include <cuda_runtime.h>
#include <cuda_bf16.h>
#include <cstdint>

#define B_ROWS 16384
#define F_DIM  512
#define H_DIM  256
#define E_NUM  8
#define OUT_DIM 32
#define DA     8
#define TM     64
#define KT     32
#define TILES  (B_ROWS / TM)   // 256
#define TMP    (TM + 1)        // padded row dim (65) to kill bank conflicts

typedef unsigned long long ull;

__device__ int g_counts[E_NUM];
__device__ int g_bucket[E_NUM][B_ROWS];

__device__ __forceinline__ ull pack2(float lo, float hi) {
    ull r;
    asm("mov.b64 %0, {%1, %2};" : "=l"(r) : "f"(lo), "f"(hi));
    return r;
}
__device__ __forceinline__ void unpack2(float& lo, float& hi, ull v) {
    asm("mov.b64 {%0, %1}, %2;" : "=f"(lo), "=f"(hi) : "l"(v));
}
__device__ __forceinline__ void ffma2(ull& d, ull a, ull b) {
    asm("fma.rn.f32x2 %0, %1, %2, %0;" : "+l"(d) : "l"(a), "l"(b));
}

__global__ void zero_counts_kernel() {
    if (threadIdx.x < E_NUM) g_counts[threadIdx.x] = 0;
}

__global__ void scatter_kernel(const int* __restrict__ ma) {
    int i = blockIdx.x * blockDim.x + threadIdx.x;
    if (i < B_ROWS) {
        int e = ma[i];
        int p = atomicAdd(&g_counts[e], 1);
        g_bucket[e][p] = i;
    }
}

// Dynamic smem layout (floats):
//   sX   [KT][TMP]        2080
//   sW   [KT][H_DIM]      8192
//   h1T  [H_DIM][TMP]    16640
//   h2T  [H_DIM][TMP]    16640
//   sW3  [H_DIM][DA]      2048
#define SMEM_FLOATS (KT*TMP + KT*H_DIM + 2*H_DIM*TMP + H_DIM*DA)

__global__ __launch_bounds__(256, 1)
void moe_kernel(const float* __restrict__ features,
                const float* __restrict__ W1, const float* __restrict__ b1,
                const float* __restrict__ W2, const float* __restrict__ b2,
                const float* __restrict__ W3, const float* __restrict__ b3,
                float* __restrict__ out)
{
    const int e    = blockIdx.y;
    const int tile = blockIdx.x;
    const int count = g_counts[e];
    const int row0 = tile * TM;
    if (row0 >= count) return;
    const int nrows = min(TM, count - row0);

    extern __shared__ float sm[];
    float* sX  = sm;                       // [KT][TMP]
    float* sW  = sX + KT * TMP;            // [KT][H_DIM]
    float* h1T = sW + KT * H_DIM;          // [H_DIM][TMP]
    float* h2T = h1T + H_DIM * TMP;        // [H_DIM][TMP]
    float* sW3 = h2T + H_DIM * TMP;        // [H_DIM][DA]
    __shared__ int   sIdx[TM];
    __shared__ float sB3[DA];

    const int t    = threadIdx.x;
    const int warp = t >> 5;
    const int lane = t & 31;
    const int rowbase = warp * 8;   // 8 rows per warp
    const int colbase = lane * 8;   // 8 cols per lane

    if (t < TM) {
        int r = (t < nrows) ? t : 0;
        sIdx[t] = g_bucket[e][row0 + r];
    }
    if (t < DA) sB3[t] = b3[e * OUT_DIM + t];
    __syncthreads();

    const float* W1e = W1 + (size_t)e * F_DIM * H_DIM;
    const float* W2e = W2 + (size_t)e * H_DIM * H_DIM;
    const float* W3e = W3 + (size_t)e * H_DIM * OUT_DIM;

    ull acc[8][4];

    // ---- init acc with b1 ----
    {
        const float* b1e = b1 + e * H_DIM + colbase;
        float4 bb0 = *(const float4*)(b1e);
        float4 bb1 = *(const float4*)(b1e + 4);
        ull p0 = pack2(bb0.x, bb0.y), p1 = pack2(bb0.z, bb0.w);
        ull p2 = pack2(bb1.x, bb1.y), p3 = pack2(bb1.z, bb1.w);
        #pragma unroll
        for (int i = 0; i < 8; i++) { acc[i][0]=p0; acc[i][1]=p1; acc[i][2]=p2; acc[i][3]=p3; }
    }

    // ================= Phase 1: h1 = relu(X @ W1 + b1) =================
    for (int k0 = 0; k0 < F_DIM; k0 += KT) {
        __syncthreads();
        // stage X tile: warp w stages rows w*8..w*8+7, lane = kk
        #pragma unroll
        for (int i = 0; i < 8; i++) {
            int r = rowbase + i;
            sX[lane * TMP + r] = features[(size_t)sIdx[r] * F_DIM + k0 + lane];
        }
        // stage W tile: fully coalesced
        #pragma unroll 4
        for (int kk = 0; kk < KT; kk++)
            sW[kk * H_DIM + t] = W1e[(size_t)(k0 + kk) * H_DIM + t];
        __syncthreads();

        #pragma unroll 4
        for (int kk = 0; kk < KT; kk++) {
            ull ap[8];
            #pragma unroll
            for (int i = 0; i < 8; i++) {
                float a = sX[kk * TMP + rowbase + i];
                ap[i] = pack2(a, a);
            }
            float4 w0 = *(const float4*)&sW[kk * H_DIM + colbase];
            float4 w1 = *(const float4*)&sW[kk * H_DIM + colbase + 4];
            ull bp[4] = { pack2(w0.x, w0.y), pack2(w0.z, w0.w),
                          pack2(w1.x, w1.y), pack2(w1.z, w1.w) };
            #pragma unroll
            for (int i = 0; i < 8; i++)
                #pragma unroll
                for (int j = 0; j < 4; j++)
                    ffma2(acc[i][j], ap[i], bp[j]);
        }
    }
    // relu + write h1 transposed [col][row]
    #pragma unroll
    for (int i = 0; i < 8; i++)
        #pragma unroll
        for (int j = 0; j < 4; j++) {
            float lo, hi; unpack2(lo, hi, acc[i][j]);
            int c = colbase + 2 * j;
            h1T[(c    ) * TMP + rowbase + i] = fmaxf(lo, 0.0f);
            h1T[(c + 1) * TMP + rowbase + i] = fmaxf(hi, 0.0f);
        }

    // ---- re-init acc with b2 ----
    {
        const float* b2e = b2 + e * H_DIM + colbase;
        float4 bb0 = *(const float4*)(b2e);
        float4 bb1 = *(const float4*)(b2e + 4);
        ull p0 = pack2(bb0.x, bb0.y), p1 = pack2(bb0.z, bb0.w);
        ull p2 = pack2(bb1.x, bb1.y), p3 = pack2(bb1.z, bb1.w);
        #pragma unroll
        for (int i = 0; i < 8; i++) { acc[i][0]=p0; acc[i][1]=p1; acc[i][2]=p2; acc[i][3]=p3; }
    }

    // ================= Phase 2: h2 = relu(h1 @ W2 + b2) =================
    for (int k0 = 0; k0 < H_DIM; k0 += KT) {
        __syncthreads();   // also orders h1T writes before cross-thread reads
        #pragma unroll 4
        for (int kk = 0; kk < KT; kk++)
            sW[kk * H_DIM + t] = W2e[(size_t)(k0 + kk) * H_DIM + t];
        __syncthreads();

        #pragma unroll 4
        for (int kk = 0; kk < KT; kk++) {
            ull ap[8];
            #pragma unroll
            for (int i = 0; i < 8; i++) {
                float a = h1T[(k0 + kk) * TMP + rowbase + i];
                ap[i] = pack2(a, a);
            }
            float4 w0 = *(const float4*)&sW[kk * H_DIM + colbase];
            float4 w1 = *(const float4*)&sW[kk * H_DIM + colbase + 4];
            ull bp[4] = { pack2(w0.x, w0.y), pack2(w0.z, w0.w),
                          pack2(w1.x, w1.y), pack2(w1.z, w1.w) };
            #pragma unroll
            for (int i = 0; i < 8; i++)
                #pragma unroll
                for (int j = 0; j < 4; j++)
                    ffma2(acc[i][j], ap[i], bp[j]);
        }
    }
    // relu + write h2 transposed
    #pragma unroll
    for (int i = 0; i < 8; i++)
        #pragma unroll
        for (int j = 0; j < 4; j++) {
            float lo, hi; unpack2(lo, hi, acc[i][j]);
            int c = colbase + 2 * j;
            h2T[(c    ) * TMP + rowbase + i] = fmaxf(lo, 0.0f);
            h2T[(c + 1) * TMP + rowbase + i] = fmaxf(hi, 0.0f);
        }

    // stage W3[:, 0:8]
    for (int q = t; q < H_DIM * DA; q += 256) {
        int k = q / DA, c = q % DA;
        sW3[q] = W3e[(size_t)k * OUT_DIM + c];
    }
    __syncthreads();

    // ================= Phase 3: y = h2 @ W3[:, :8] + b3, scatter =================
    #pragma unroll
    for (int half = 0; half < 2; half++) {
        int o = t + half * 256;        // 512 outputs total
        int r = o >> 3;
        int c = o & 7;
        float s = sB3[c];
        #pragma unroll 8
        for (int k = 0; k < H_DIM; k++)
            s = fmaf(h2T[k * TMP + r], sW3[k * DA + c], s);
        if (r < nrows)
            out[(size_t)sIdx[r] * DA + c] = s;
    }
}

extern "C" void kernel_launch(void* const* d_in, const int* in_sizes, int n_in,
                              void* d_out, int out_size)
{
    const float* features = (const float*)d_in[0];
    const float* W1 = (const float*)d_in[1];
    const float* b1 = (const float*)d_in[2];
    const float* W2 = (const float*)d_in[3];
    const float* b2 = (const float*)d_in[4];
    const float* W3 = (const float*)d_in[5];
    const float* b3 = (const float*)d_in[6];
    const int*   ma = (const int*)d_in[7];   // JAX w/o x64: int64 request -> int32 on device
    float* out = (float*)d_out;

    size_t smem_bytes = (size_t)SMEM_FLOATS * sizeof(float);
    cudaFuncSetAttribute(moe_kernel, cudaFuncAttributeMaxDynamicSharedMemorySize,
                         (int)smem_bytes);

    zero_counts_kernel<<<1, 32>>>();
    scatter_kernel<<<B_ROWS / 256, 256>>>(ma);
    moe_kernel<<<dim3(TILES, E_NUM), 256, smem_bytes>>>(features, W1, b1, W2, b2,
                                                        W3, b3, out);
}

// round 5
// speedup vs baseline: 2.2965x; 2.2965x over previous
#include <cuda_runtime.h>
#include <cuda_bf16.h>
#include <cstdint>

#define B_ROWS 16384
#define F_DIM  512
#define H_DIM  256
#define E_NUM  8
#define OUT_DIM 32
#define DA     8
#define TM     128
#define NTILES (B_ROWS / TM)   // 128

#define ASTR 36    // b32 stride for 64-bf16 staged tiles (32 + 4 pad) -> conflict-free frags
#define HSTR 132   // b32 stride for 256-bf16 h tiles (128 + 4 pad)

// ---------------- device scratch ----------------
__device__ int g_counts[E_NUM];
__device__ int g_bucket[E_NUM][B_ROWS];

__device__ __align__(16) __nv_bfloat16 g_W1T_hi[E_NUM][H_DIM][F_DIM];
__device__ __align__(16) __nv_bfloat16 g_W1T_lo[E_NUM][H_DIM][F_DIM];
__device__ __align__(16) __nv_bfloat16 g_W2T_hi[E_NUM][H_DIM][H_DIM];
__device__ __align__(16) __nv_bfloat16 g_W2T_lo[E_NUM][H_DIM][H_DIM];
__device__ __align__(16) __nv_bfloat16 g_W3T_hi[E_NUM][OUT_DIM][H_DIM];
__device__ __align__(16) __nv_bfloat16 g_W3T_lo[E_NUM][OUT_DIM][H_DIM];

__device__ __forceinline__ void split1(float x, __nv_bfloat16& h, __nv_bfloat16& l) {
    h = __float2bfloat16_rn(x);
    l = __float2bfloat16_rn(x - __bfloat162float(h));
}
__device__ __forceinline__ uint32_t packbf(__nv_bfloat16 a, __nv_bfloat16 b) {
    __nv_bfloat162 t(a, b);
    return *reinterpret_cast<uint32_t*>(&t);
}
__device__ __forceinline__ void split_pack(float v0, float v1, uint32_t& hp, uint32_t& lp) {
    __nv_bfloat16 h0, l0, h1, l1;
    split1(v0, h0, l0); split1(v1, h1, l1);
    hp = packbf(h0, h1);
    lp = packbf(l0, l1);
}

__device__ __forceinline__ void mma16816(float* d, const uint32_t* a, const uint32_t* b) {
    asm volatile("mma.sync.aligned.m16n8k16.row.col.f32.bf16.bf16.f32 "
        "{%0,%1,%2,%3}, {%4,%5,%6,%7}, {%8,%9}, {%0,%1,%2,%3};"
        : "+f"(d[0]), "+f"(d[1]), "+f"(d[2]), "+f"(d[3])
        : "r"(a[0]), "r"(a[1]), "r"(a[2]), "r"(a[3]), "r"(b[0]), "r"(b[1]));
}

// One 64-wide K chunk of warp-tile (32 rows x 64 cols) MMA with bf16x3 split.
template<int LDA, int LDB>
__device__ __forceinline__ void mma_chunk64(
    float acc[2][8][4],
    const uint32_t* __restrict__ aHi, const uint32_t* __restrict__ aLo,
    const uint32_t* __restrict__ bHi, const uint32_t* __restrict__ bLo,
    int gid, int tig)
{
    #pragma unroll
    for (int ks = 0; ks < 4; ks++) {
        const int kb = ks * 8 + tig;
        uint32_t ah[2][4], al[2][4];
        #pragma unroll
        for (int mi = 0; mi < 2; mi++) {
            const uint32_t* pH = aHi + (mi * 16 + gid) * LDA + kb;
            const uint32_t* pL = aLo + (mi * 16 + gid) * LDA + kb;
            ah[mi][0] = pH[0]; ah[mi][1] = pH[8 * LDA]; ah[mi][2] = pH[4]; ah[mi][3] = pH[8 * LDA + 4];
            al[mi][0] = pL[0]; al[mi][1] = pL[8 * LDA]; al[mi][2] = pL[4]; al[mi][3] = pL[8 * LDA + 4];
        }
        #pragma unroll
        for (int ni = 0; ni < 8; ni++) {
            const uint32_t* qH = bHi + (ni * 8 + gid) * LDB + kb;
            const uint32_t* qL = bLo + (ni * 8 + gid) * LDB + kb;
            uint32_t bh[2] = { qH[0], qH[4] };
            uint32_t bl[2] = { qL[0], qL[4] };
            #pragma unroll
            for (int mi = 0; mi < 2; mi++) {
                mma16816(acc[mi][ni], ah[mi], bh);
                mma16816(acc[mi][ni], ah[mi], bl);
                mma16816(acc[mi][ni], al[mi], bh);
            }
        }
    }
}

// ---------------- prep kernels ----------------
__global__ void zero_counts_kernel() {
    if (threadIdx.x < E_NUM) g_counts[threadIdx.x] = 0;
}
__global__ void scatter_kernel(const int* __restrict__ ma) {
    int i = blockIdx.x * blockDim.x + threadIdx.x;
    if (i < B_ROWS) {
        int e = ma[i];
        int p = atomicAdd(&g_counts[e], 1);
        g_bucket[e][p] = i;
    }
}

// transpose + bf16 split: W[K,N] -> WT_hi/lo[N,K]
__global__ void prep_weights(const float* __restrict__ W1,
                             const float* __restrict__ W2,
                             const float* __restrict__ W3) {
    int z = blockIdx.z, e = blockIdx.y;
    int Kd = (z == 0) ? F_DIM : H_DIM;
    int Nd = (z == 0) ? H_DIM : ((z == 1) ? H_DIM : OUT_DIM);
    int ntn = Nd / 32;
    int tk = (blockIdx.x / ntn) * 32;
    int tn = (blockIdx.x % ntn) * 32;
    if (tk >= Kd) return;
    const float* src = ((z == 0) ? W1 : (z == 1) ? W2 : W3) + (size_t)e * Kd * Nd;
    __nv_bfloat16* dh = (z == 0) ? &g_W1T_hi[e][0][0] : (z == 1) ? &g_W2T_hi[e][0][0] : &g_W3T_hi[e][0][0];
    __nv_bfloat16* dl = (z == 0) ? &g_W1T_lo[e][0][0] : (z == 1) ? &g_W2T_lo[e][0][0] : &g_W3T_lo[e][0][0];
    __shared__ float tile[32][33];
    int tx = threadIdx.x, ty = threadIdx.y;   // 32 x 8
    #pragma unroll
    for (int r = 0; r < 4; r++)
        tile[ty + r * 8][tx] = src[(size_t)(tk + ty + r * 8) * Nd + tn + tx];
    __syncthreads();
    #pragma unroll
    for (int r = 0; r < 4; r++) {
        int n = tn + ty + r * 8, k = tk + tx;
        float v = tile[tx][ty + r * 8];
        __nv_bfloat16 h, l; split1(v, h, l);
        dh[(size_t)n * Kd + k] = h;
        dl[(size_t)n * Kd + k] = l;
    }
}

// ---------------- smem layout (in b32 words) ----------------
#define OFF_HHI 0
#define OFF_HLO (OFF_HHI + 128 * HSTR)            // 16896
#define OFF_AHI (OFF_HLO + 128 * HSTR)            // 33792
#define OFF_ALO (OFF_AHI + 128 * ASTR)            // 38400
#define OFF_BHI (OFF_ALO + 128 * ASTR)            // 43008
#define OFF_BLO (OFF_BHI + 128 * ASTR)            // 47616
#define SMEM_WORDS (OFF_BLO + 128 * ASTR)         // 52224 -> 208896 bytes

// ---------------- main MMA kernel ----------------
__global__ __launch_bounds__(256, 1)
void moe_mma_kernel(const float* __restrict__ features,
                    const float* __restrict__ b1,
                    const float* __restrict__ b2,
                    const float* __restrict__ b3,
                    float* __restrict__ out)
{
    const int e = blockIdx.y;
    const int count = g_counts[e];
    const int row0 = blockIdx.x * TM;
    if (row0 >= count) return;
    const int nrows = min(TM, count - row0);

    extern __shared__ uint32_t sm[];
    uint32_t* hHi = sm + OFF_HHI;
    uint32_t* hLo = sm + OFF_HLO;
    uint32_t* aHi = sm + OFF_AHI;
    uint32_t* aLo = sm + OFF_ALO;
    uint32_t* bHi = sm + OFF_BHI;
    uint32_t* bLo = sm + OFF_BLO;

    __shared__ int   sIdx[TM];
    __shared__ float sB1[H_DIM];
    __shared__ float sB2[H_DIM];
    __shared__ float sB3[DA];

    const int t    = threadIdx.x;
    const int wid  = t >> 5;
    const int lane = t & 31;
    const int gid  = lane >> 2;     // 0..7
    const int tig  = lane & 3;      // 0..3
    const int wrow = wid & 3;       // 4 row-warps * 32 rows
    const int wcol = wid >> 2;      // 2 col-warps * 64 cols

    if (t < TM) sIdx[t] = g_bucket[e][row0 + min(t, nrows - 1)];
    sB1[t] = b1[e * H_DIM + t];
    sB2[t] = b2[e * H_DIM + t];
    if (t < DA) sB3[t] = b3[e * OUT_DIM + t];
    __syncthreads();

    const int srow = t >> 1;        // staging row (0..127)
    const int sseg = t & 1;         // which 32-element half
    const float* frow = features + (size_t)sIdx[srow] * F_DIM;

    const __nv_bfloat16* w1h = &g_W1T_hi[e][0][0];
    const __nv_bfloat16* w1l = &g_W1T_lo[e][0][0];
    const __nv_bfloat16* w2h = &g_W2T_hi[e][0][0];
    const __nv_bfloat16* w2l = &g_W2T_lo[e][0][0];
    const __nv_bfloat16* w3h = &g_W3T_hi[e][0][0];
    const __nv_bfloat16* w3l = &g_W3T_lo[e][0][0];

    const uint32_t* aW   = aHi + wrow * 32 * ASTR;
    const uint32_t* aWlo = aLo + wrow * 32 * ASTR;
    const uint32_t* bW   = bHi + wcol * 64 * ASTR;
    const uint32_t* bWlo = bLo + wcol * 64 * ASTR;

    // =================== Layer 1: h1 = relu(X @ W1 + b1) ===================
    #pragma unroll 1
    for (int nh = 0; nh < 2; nh++) {
        float acc[2][8][4];
        #pragma unroll
        for (int mi = 0; mi < 2; mi++)
            #pragma unroll
            for (int ni = 0; ni < 8; ni++)
                #pragma unroll
                for (int c = 0; c < 4; c++) acc[mi][ni][c] = 0.f;

        #pragma unroll 1
        for (int kc = 0; kc < F_DIM / 64; kc++) {
            __syncthreads();
            // stage A: gather features rows, split fp32 -> bf16 hi/lo (32 floats/thread)
            {
                const float* src = frow + kc * 64 + sseg * 32;
                #pragma unroll
                for (int j = 0; j < 8; j++) {
                    float4 v = *(const float4*)(src + j * 4);
                    uint32_t h0, l0, h1, l1;
                    split_pack(v.x, v.y, h0, l0);
                    split_pack(v.z, v.w, h1, l1);
                    int o = srow * ASTR + sseg * 16 + j * 2;
                    aHi[o] = h0; aHi[o + 1] = h1;
                    aLo[o] = l0; aLo[o + 1] = l1;
                }
            }
            // stage B: W1T rows [nh*128 .. +128), full 32 bf16 per (row,half)
            {
                int n = srow;
                const uint4* sh = (const uint4*)(w1h + (size_t)(nh * 128 + n) * F_DIM + kc * 64 + sseg * 32);
                const uint4* sl = (const uint4*)(w1l + (size_t)(nh * 128 + n) * F_DIM + kc * 64 + sseg * 32);
                #pragma unroll
                for (int j = 0; j < 4; j++) {
                    *(uint4*)&bHi[n * ASTR + sseg * 16 + j * 4] = sh[j];
                    *(uint4*)&bLo[n * ASTR + sseg * 16 + j * 4] = sl[j];
                }
            }
            __syncthreads();
            mma_chunk64<ASTR, ASTR>(acc, aW, aWlo, bW, bWlo, gid, tig);
        }
        // epilogue: relu + bias -> h (bf16 hi/lo pairs)
        #pragma unroll
        for (int mi = 0; mi < 2; mi++) {
            int r0 = wrow * 32 + mi * 16 + gid;
            #pragma unroll
            for (int ni = 0; ni < 8; ni++) {
                int col = nh * 128 + wcol * 64 + ni * 8 + 2 * tig;
                int cp  = col >> 1;
                float v0 = fmaxf(acc[mi][ni][0] + sB1[col], 0.f);
                float v1 = fmaxf(acc[mi][ni][1] + sB1[col + 1], 0.f);
                float v2 = fmaxf(acc[mi][ni][2] + sB1[col], 0.f);
                float v3 = fmaxf(acc[mi][ni][3] + sB1[col + 1], 0.f);
                uint32_t hp, lp;
                split_pack(v0, v1, hp, lp);
                hHi[r0 * HSTR + cp] = hp; hLo[r0 * HSTR + cp] = lp;
                split_pack(v2, v3, hp, lp);
                hHi[(r0 + 8) * HSTR + cp] = hp; hLo[(r0 + 8) * HSTR + cp] = lp;
            }
        }
    }
    __syncthreads();

    // =================== Layer 2: h2 = relu(h1 @ W2 + b2) ===================
    uint32_t keepH[2][8][2], keepL[2][8][2];
    {
        float acc[2][8][4];
        #pragma unroll 1
        for (int nh = 0; nh < 2; nh++) {
            #pragma unroll
            for (int mi = 0; mi < 2; mi++)
                #pragma unroll
                for (int ni = 0; ni < 8; ni++)
                    #pragma unroll
                    for (int c = 0; c < 4; c++) acc[mi][ni][c] = 0.f;

            #pragma unroll 1
            for (int kc = 0; kc < H_DIM / 64; kc++) {
                __syncthreads();
                int n = srow;
                const uint4* sh = (const uint4*)(w2h + (size_t)(nh * 128 + n) * H_DIM + kc * 64 + sseg * 32);
                const uint4* sl = (const uint4*)(w2l + (size_t)(nh * 128 + n) * H_DIM + kc * 64 + sseg * 32);
                #pragma unroll
                for (int j = 0; j < 4; j++) {
                    *(uint4*)&bHi[n * ASTR + sseg * 16 + j * 4] = sh[j];
                    *(uint4*)&bLo[n * ASTR + sseg * 16 + j * 4] = sl[j];
                }
                __syncthreads();
                mma_chunk64<HSTR, ASTR>(acc,
                    hHi + wrow * 32 * HSTR + kc * 32,
                    hLo + wrow * 32 * HSTR + kc * 32,
                    bW, bWlo, gid, tig);
            }
            // pack with relu+bias
            #pragma unroll
            for (int mi = 0; mi < 2; mi++) {
                #pragma unroll
                for (int ni = 0; ni < 8; ni++) {
                    int col = nh * 128 + wcol * 64 + ni * 8 + 2 * tig;
                    float v0 = fmaxf(acc[mi][ni][0] + sB2[col], 0.f);
                    float v1 = fmaxf(acc[mi][ni][1] + sB2[col + 1], 0.f);
                    float v2 = fmaxf(acc[mi][ni][2] + sB2[col], 0.f);
                    float v3 = fmaxf(acc[mi][ni][3] + sB2[col + 1], 0.f);
                    if (nh == 0) {
                        split_pack(v0, v1, keepH[mi][ni][0], keepL[mi][ni][0]);
                        split_pack(v2, v3, keepH[mi][ni][1], keepL[mi][ni][1]);
                    } else {
                        uint32_t hp, lp;
                        split_pack(v0, v1, hp, lp);
                        acc[mi][ni][0] = __uint_as_float(hp);
                        acc[mi][ni][1] = __uint_as_float(lp);
                        split_pack(v2, v3, hp, lp);
                        acc[mi][ni][2] = __uint_as_float(hp);
                        acc[mi][ni][3] = __uint_as_float(lp);
                    }
                }
            }
        }
        __syncthreads();   // all h1 reads complete; safe to overwrite h
        #pragma unroll
        for (int mi = 0; mi < 2; mi++) {
            int r0 = wrow * 32 + mi * 16 + gid;
            #pragma unroll
            for (int ni = 0; ni < 8; ni++) {
                int cp0 = (wcol * 64 + ni * 8 + 2 * tig) >> 1;        // half 0
                int cp1 = cp0 + 64;                                   // half 1
                hHi[r0 * HSTR + cp0] = keepH[mi][ni][0];
                hLo[r0 * HSTR + cp0] = keepL[mi][ni][0];
                hHi[(r0 + 8) * HSTR + cp0] = keepH[mi][ni][1];
                hLo[(r0 + 8) * HSTR + cp0] = keepL[mi][ni][1];
                hHi[r0 * HSTR + cp1] = __float_as_uint(acc[mi][ni][0]);
                hLo[r0 * HSTR + cp1] = __float_as_uint(acc[mi][ni][1]);
                hHi[(r0 + 8) * HSTR + cp1] = __float_as_uint(acc[mi][ni][2]);
                hLo[(r0 + 8) * HSTR + cp1] = __float_as_uint(acc[mi][ni][3]);
            }
        }
    }

    // stage W3T rows 0..7 (only first 8 output cols needed), full K=256
    if (t < 64) {
        int n = t >> 3, i = (t & 7) * 16;   // i in b32 (128 per row)
        const uint4* sh = (const uint4*)(w3h + (size_t)n * H_DIM + i * 2);
        const uint4* sl = (const uint4*)(w3l + (size_t)n * H_DIM + i * 2);
        #pragma unroll
        for (int j = 0; j < 4; j++) {
            *(uint4*)&bHi[n * HSTR + i + j * 4] = sh[j];
            *(uint4*)&bLo[n * HSTR + i + j * 4] = sl[j];
        }
    }
    __syncthreads();

    // =================== Layer 3: y = h2 @ W3[:, :8] + b3 ===================
    {
        float acc3[4] = {0.f, 0.f, 0.f, 0.f};
        const uint32_t* pAh = hHi + wid * 16 * HSTR;
        const uint32_t* pAl = hLo + wid * 16 * HSTR;
        #pragma unroll
        for (int ks = 0; ks < 16; ks++) {
            const int kb = ks * 8 + tig;
            uint32_t ah[4], al[4];
            ah[0] = pAh[gid * HSTR + kb];       ah[1] = pAh[(gid + 8) * HSTR + kb];
            ah[2] = pAh[gid * HSTR + kb + 4];   ah[3] = pAh[(gid + 8) * HSTR + kb + 4];
            al[0] = pAl[gid * HSTR + kb];       al[1] = pAl[(gid + 8) * HSTR + kb];
            al[2] = pAl[gid * HSTR + kb + 4];   al[3] = pAl[(gid + 8) * HSTR + kb + 4];
            uint32_t bh[2] = { bHi[gid * HSTR + kb], bHi[gid * HSTR + kb + 4] };
            uint32_t bl[2] = { bLo[gid * HSTR + kb], bLo[gid * HSTR + kb + 4] };
            mma16816(acc3, ah, bh);
            mma16816(acc3, ah, bl);
            mma16816(acc3, al, bh);
        }
        int r0 = wid * 16 + gid;
        int c  = 2 * tig;
        if (r0 < nrows) {
            float* o = out + (size_t)sIdx[r0] * DA + c;
            o[0] = acc3[0] + sB3[c];
            o[1] = acc3[1] + sB3[c + 1];
        }
        if (r0 + 8 < nrows) {
            float* o = out + (size_t)sIdx[r0 + 8] * DA + c;
            o[0] = acc3[2] + sB3[c];
            o[1] = acc3[3] + sB3[c + 1];
        }
    }
}

extern "C" void kernel_launch(void* const* d_in, const int* in_sizes, int n_in,
                              void* d_out, int out_size)
{
    const float* features = (const float*)d_in[0];
    const float* W1 = (const float*)d_in[1];
    const float* b1 = (const float*)d_in[2];
    const float* W2 = (const float*)d_in[3];
    const float* b2 = (const float*)d_in[4];
    const float* W3 = (const float*)d_in[5];
    const float* b3 = (const float*)d_in[6];
    const int*   ma = (const int*)d_in[7];
    float* out = (float*)d_out;

    cudaFuncSetAttribute(moe_mma_kernel, cudaFuncAttributeMaxDynamicSharedMemorySize,
                         SMEM_WORDS * 4);

    zero_counts_kernel<<<1, 32>>>();
    scatter_kernel<<<B_ROWS / 256, 256>>>(ma);
    prep_weights<<<dim3(128, E_NUM, 3), dim3(32, 8)>>>(W1, W2, W3);
    moe_mma_kernel<<<dim3(NTILES, E_NUM), 256, SMEM_WORDS * 4>>>(features, b1, b2, b3, out);
}

// round 6
// speedup vs baseline: 3.1940x; 1.3908x over previous
#include <cuda_runtime.h>
#include <cuda_bf16.h>
#include <cstdint>

#define B_ROWS 16384
#define F_DIM  512
#define H_DIM  256
#define E_NUM  8
#define OUT_DIM 32
#define DA     8
#define TM     128
#define NTILES (B_ROWS / TM)   // 128

#define ASTR 36    // b32 stride, 64-bf16 staged rows (32 words + 4 pad)
#define HSTR 132   // b32 stride, 256-bf16 h rows (128 words + 4 pad)

// ---------------- device scratch ----------------
__device__ int g_counts[E_NUM];
__device__ int g_bucket[E_NUM][B_ROWS];

__device__ __align__(16) __nv_bfloat16 g_W1T_hi[E_NUM][H_DIM][F_DIM];
__device__ __align__(16) __nv_bfloat16 g_W1T_lo[E_NUM][H_DIM][F_DIM];
__device__ __align__(16) __nv_bfloat16 g_W2T_hi[E_NUM][H_DIM][H_DIM];
__device__ __align__(16) __nv_bfloat16 g_W2T_lo[E_NUM][H_DIM][H_DIM];
__device__ __align__(16) __nv_bfloat16 g_W3T_hi[E_NUM][OUT_DIM][H_DIM];
__device__ __align__(16) __nv_bfloat16 g_W3T_lo[E_NUM][OUT_DIM][H_DIM];

__device__ __forceinline__ void split1(float x, __nv_bfloat16& h, __nv_bfloat16& l) {
    h = __float2bfloat16_rn(x);
    l = __float2bfloat16_rn(x - __bfloat162float(h));
}
__device__ __forceinline__ uint32_t packbf(__nv_bfloat16 a, __nv_bfloat16 b) {
    __nv_bfloat162 t(a, b);
    return *reinterpret_cast<uint32_t*>(&t);
}
__device__ __forceinline__ void split_pack(float v0, float v1, uint32_t& hp, uint32_t& lp) {
    __nv_bfloat16 h0, l0, h1, l1;
    split1(v0, h0, l0); split1(v1, h1, l1);
    hp = packbf(h0, h1);
    lp = packbf(l0, l1);
}

__device__ __forceinline__ uint32_t smem_u32(const void* p) {
    uint32_t a;
    asm("{ .reg .u64 t; cvta.to.shared.u64 t, %1; cvt.u32.u64 %0, t; }" : "=r"(a) : "l"(p));
    return a;
}
__device__ __forceinline__ void cpasync16(uint32_t dst, const void* src) {
    asm volatile("cp.async.cg.shared.global [%0], [%1], 16;" :: "r"(dst), "l"(src));
}
#define CP_COMMIT_WAIT() do { \
    asm volatile("cp.async.commit_group;"); \
    asm volatile("cp.async.wait_group 0;"); } while (0)

__device__ __forceinline__ void mma16816(float* d, const uint32_t* a, const uint32_t* b) {
    asm volatile("mma.sync.aligned.m16n8k16.row.col.f32.bf16.bf16.f32 "
        "{%0,%1,%2,%3}, {%4,%5,%6,%7}, {%8,%9}, {%0,%1,%2,%3};"
        : "+f"(d[0]), "+f"(d[1]), "+f"(d[2]), "+f"(d[3])
        : "r"(a[0]), "r"(a[1]), "r"(a[2]), "r"(a[3]), "r"(b[0]), "r"(b[1]));
}

// One 64-wide K chunk of warp-tile (32 rows x 64 cols), bf16x3 split.
template<int LDA, int LDB>
__device__ __forceinline__ void mma_chunk64(
    float acc[2][8][4],
    const uint32_t* __restrict__ aHi, const uint32_t* __restrict__ aLo,
    const uint32_t* __restrict__ bHi, const uint32_t* __restrict__ bLo,
    int gid, int tig)
{
    #pragma unroll
    for (int ks = 0; ks < 4; ks++) {
        const int kb = ks * 8 + tig;
        uint32_t ah[2][4], al[2][4];
        #pragma unroll
        for (int mi = 0; mi < 2; mi++) {
            const uint32_t* pH = aHi + (mi * 16 + gid) * LDA + kb;
            const uint32_t* pL = aLo + (mi * 16 + gid) * LDA + kb;
            ah[mi][0] = pH[0]; ah[mi][1] = pH[8 * LDA]; ah[mi][2] = pH[4]; ah[mi][3] = pH[8 * LDA + 4];
            al[mi][0] = pL[0]; al[mi][1] = pL[8 * LDA]; al[mi][2] = pL[4]; al[mi][3] = pL[8 * LDA + 4];
        }
        #pragma unroll
        for (int ni = 0; ni < 8; ni++) {
            const uint32_t* qH = bHi + (ni * 8 + gid) * LDB + kb;
            const uint32_t* qL = bLo + (ni * 8 + gid) * LDB + kb;
            uint32_t bh[2] = { qH[0], qH[4] };
            uint32_t bl[2] = { qL[0], qL[4] };
            #pragma unroll
            for (int mi = 0; mi < 2; mi++) {
                mma16816(acc[mi][ni], ah[mi], bh);
                mma16816(acc[mi][ni], ah[mi], bl);
                mma16816(acc[mi][ni], al[mi], bh);
            }
        }
    }
}

// ---------------- prep kernels ----------------
__global__ void zero_counts_kernel() {
    if (threadIdx.x < E_NUM) g_counts[threadIdx.x] = 0;
}
__global__ void scatter_kernel(const int* __restrict__ ma) {
    int i = blockIdx.x * blockDim.x + threadIdx.x;
    if (i < B_ROWS) {
        int e = ma[i];
        int p = atomicAdd(&g_counts[e], 1);
        g_bucket[e][p] = i;
    }
}
__global__ void prep_weights(const float* __restrict__ W1,
                             const float* __restrict__ W2,
                             const float* __restrict__ W3) {
    int z = blockIdx.z, e = blockIdx.y;
    int Kd = (z == 0) ? F_DIM : H_DIM;
    int Nd = (z == 0) ? H_DIM : ((z == 1) ? H_DIM : OUT_DIM);
    int ntn = Nd / 32;
    int tk = (blockIdx.x / ntn) * 32;
    int tn = (blockIdx.x % ntn) * 32;
    if (tk >= Kd) return;
    const float* src = ((z == 0) ? W1 : (z == 1) ? W2 : W3) + (size_t)e * Kd * Nd;
    __nv_bfloat16* dh = (z == 0) ? &g_W1T_hi[e][0][0] : (z == 1) ? &g_W2T_hi[e][0][0] : &g_W3T_hi[e][0][0];
    __nv_bfloat16* dl = (z == 0) ? &g_W1T_lo[e][0][0] : (z == 1) ? &g_W2T_lo[e][0][0] : &g_W3T_lo[e][0][0];
    __shared__ float tile[32][33];
    int tx = threadIdx.x, ty = threadIdx.y;   // 32 x 8
    #pragma unroll
    for (int r = 0; r < 4; r++)
        tile[ty + r * 8][tx] = src[(size_t)(tk + ty + r * 8) * Nd + tn + tx];
    __syncthreads();
    #pragma unroll
    for (int r = 0; r < 4; r++) {
        int n = tn + ty + r * 8, k = tk + tx;
        float v = tile[tx][ty + r * 8];
        __nv_bfloat16 h, l; split1(v, h, l);
        dh[(size_t)n * Kd + k] = h;
        dl[(size_t)n * Kd + k] = l;
    }
}

// ---------------- smem layout (b32 words) ----------------
// B staging: 256 rows x ASTR, hi+lo
#define OFF_BHI 0
#define OFF_BLO (OFF_BHI + 256 * ASTR)            // 9216
#define OFF_H   (OFF_BLO + 256 * ASTR)            // 18432
// h tiles (hi then lo), 128 x HSTR each. A staging ALIASES the start of hHi
// (A is dead before the first h write; a __syncthreads separates them).
#define OFF_HHI OFF_H
#define OFF_HLO (OFF_H + 128 * HSTR)              // 35328
#define OFF_AHI OFF_H
#define OFF_ALO (OFF_H + 128 * ASTR)              // 23040 (inside hHi)
#define SMEM_WORDS (OFF_HLO + 128 * HSTR)         // 52224 -> 208896 bytes

// ---------------- main MMA kernel: 512 threads, 4x4 warps ----------------
__global__ __launch_bounds__(512, 1)
void moe_mma_kernel(const float* __restrict__ features,
                    const float* __restrict__ b1,
                    const float* __restrict__ b2,
                    const float* __restrict__ b3,
                    float* __restrict__ out)
{
    const int e = blockIdx.y;
    const int count = g_counts[e];
    const int row0 = blockIdx.x * TM;
    if (row0 >= count) return;
    const int nrows = min(TM, count - row0);

    extern __shared__ uint32_t sm[];
    uint32_t* bHi = sm + OFF_BHI;
    uint32_t* bLo = sm + OFF_BLO;
    uint32_t* aHi = sm + OFF_AHI;
    uint32_t* aLo = sm + OFF_ALO;
    uint32_t* hHi = sm + OFF_HHI;
    uint32_t* hLo = sm + OFF_HLO;
    const uint32_t sb = smem_u32(sm);

    __shared__ int   sIdx[TM];
    __shared__ float sB1[H_DIM];
    __shared__ float sB2[H_DIM];
    __shared__ float sB3[DA];

    const int t    = threadIdx.x;
    const int wid  = t >> 5;
    const int lane = t & 31;
    const int gid  = lane >> 2;     // 0..7
    const int tig  = lane & 3;      // 0..3
    const int wrow = wid & 3;       // 4 row-warps * 32 rows
    const int wcol = wid >> 2;      // 4 col-warps * 64 cols

    if (t < TM) sIdx[t] = g_bucket[e][row0 + min(t, nrows - 1)];
    if (t < H_DIM) {
        sB1[t] = b1[e * H_DIM + t];
        sB2[t] = b2[e * H_DIM + t];
    }
    if (t < DA) sB3[t] = b3[e * OUT_DIM + t];
    __syncthreads();

    // staging roles
    const int arow = t >> 2;        // 0..127 (A rows)
    const int aseg = t & 3;         // 16 floats each
    const int brow = t >> 1;        // 0..255 (B rows)
    const int bhalf = t & 1;        // 4 x 16B chunks each
    const float* frow = features + (size_t)sIdx[arow] * F_DIM;

    const __nv_bfloat16* w1h = &g_W1T_hi[e][0][0];
    const __nv_bfloat16* w1l = &g_W1T_lo[e][0][0];
    const __nv_bfloat16* w2h = &g_W2T_hi[e][0][0];
    const __nv_bfloat16* w2l = &g_W2T_lo[e][0][0];
    const __nv_bfloat16* w3h = &g_W3T_hi[e][0][0];
    const __nv_bfloat16* w3l = &g_W3T_lo[e][0][0];

    const uint32_t* aW   = aHi + wrow * 32 * ASTR;
    const uint32_t* aWlo = aLo + wrow * 32 * ASTR;
    const uint32_t* bW   = bHi + wcol * 64 * ASTR;
    const uint32_t* bWlo = bLo + wcol * 64 * ASTR;

    const uint32_t bDstHi = sb + OFF_BHI * 4 + brow * (ASTR * 4) + bhalf * 64;
    const uint32_t bDstLo = sb + OFF_BLO * 4 + brow * (ASTR * 4) + bhalf * 64;

    float acc[2][8][4];
    #pragma unroll
    for (int mi = 0; mi < 2; mi++)
        #pragma unroll
        for (int ni = 0; ni < 8; ni++)
            #pragma unroll
            for (int c = 0; c < 4; c++) acc[mi][ni][c] = 0.f;

    // =================== Layer 1: h1 = relu(X @ W1 + b1) ===================
    #pragma unroll 1
    for (int kc = 0; kc < F_DIM / 64; kc++) {
        __syncthreads();
        // B: cp.async 4x16B hi + 4x16B lo per thread (256 rows x 64 bf16)
        {
            const __nv_bfloat16* sh = w1h + (size_t)brow * F_DIM + kc * 64 + bhalf * 32;
            const __nv_bfloat16* sl = w1l + (size_t)brow * F_DIM + kc * 64 + bhalf * 32;
            #pragma unroll
            for (int c = 0; c < 4; c++) {
                cpasync16(bDstHi + c * 16, sh + c * 8);
                cpasync16(bDstLo + c * 16, sl + c * 8);
            }
        }
        // A: gather + split 16 floats per thread
        {
            const float* src = frow + kc * 64 + aseg * 16;
            #pragma unroll
            for (int j = 0; j < 4; j++) {
                float4 v = *(const float4*)(src + j * 4);
                uint32_t h0, l0, h1, l1;
                split_pack(v.x, v.y, h0, l0);
                split_pack(v.z, v.w, h1, l1);
                int o = arow * ASTR + aseg * 8 + j * 2;
                aHi[o] = h0; aHi[o + 1] = h1;
                aLo[o] = l0; aLo[o + 1] = l1;
            }
        }
        CP_COMMIT_WAIT();
        __syncthreads();
        mma_chunk64<ASTR, ASTR>(acc, aW, aWlo, bW, bWlo, gid, tig);
    }
    __syncthreads();   // all A reads done; safe to write h (aliases A)

    // epilogue 1: relu + bias -> h
    #pragma unroll
    for (int mi = 0; mi < 2; mi++) {
        int r0 = wrow * 32 + mi * 16 + gid;
        #pragma unroll
        for (int ni = 0; ni < 8; ni++) {
            int col = wcol * 64 + ni * 8 + 2 * tig;
            int cp  = col >> 1;
            float v0 = fmaxf(acc[mi][ni][0] + sB1[col], 0.f);
            float v1 = fmaxf(acc[mi][ni][1] + sB1[col + 1], 0.f);
            float v2 = fmaxf(acc[mi][ni][2] + sB1[col], 0.f);
            float v3 = fmaxf(acc[mi][ni][3] + sB1[col + 1], 0.f);
            uint32_t hp, lp;
            split_pack(v0, v1, hp, lp);
            hHi[r0 * HSTR + cp] = hp; hLo[r0 * HSTR + cp] = lp;
            split_pack(v2, v3, hp, lp);
            hHi[(r0 + 8) * HSTR + cp] = hp; hLo[(r0 + 8) * HSTR + cp] = lp;
            acc[mi][ni][0] = 0.f; acc[mi][ni][1] = 0.f;
            acc[mi][ni][2] = 0.f; acc[mi][ni][3] = 0.f;
        }
    }

    // =================== Layer 2: h2 = relu(h1 @ W2 + b2) ===================
    #pragma unroll 1
    for (int kc = 0; kc < H_DIM / 64; kc++) {
        __syncthreads();   // first iter also publishes h writes
        {
            const __nv_bfloat16* sh = w2h + (size_t)brow * H_DIM + kc * 64 + bhalf * 32;
            const __nv_bfloat16* sl = w2l + (size_t)brow * H_DIM + kc * 64 + bhalf * 32;
            #pragma unroll
            for (int c = 0; c < 4; c++) {
                cpasync16(bDstHi + c * 16, sh + c * 8);
                cpasync16(bDstLo + c * 16, sl + c * 8);
            }
        }
        CP_COMMIT_WAIT();
        __syncthreads();
        mma_chunk64<HSTR, ASTR>(acc,
            hHi + wrow * 32 * HSTR + kc * 32,
            hLo + wrow * 32 * HSTR + kc * 32,
            bW, bWlo, gid, tig);
    }
    __syncthreads();   // all h1 reads done; safe to overwrite h

    // epilogue 2: relu + bias -> h (overwrite)
    #pragma unroll
    for (int mi = 0; mi < 2; mi++) {
        int r0 = wrow * 32 + mi * 16 + gid;
        #pragma unroll
        for (int ni = 0; ni < 8; ni++) {
            int col = wcol * 64 + ni * 8 + 2 * tig;
            int cp  = col >> 1;
            float v0 = fmaxf(acc[mi][ni][0] + sB2[col], 0.f);
            float v1 = fmaxf(acc[mi][ni][1] + sB2[col + 1], 0.f);
            float v2 = fmaxf(acc[mi][ni][2] + sB2[col], 0.f);
            float v3 = fmaxf(acc[mi][ni][3] + sB2[col + 1], 0.f);
            uint32_t hp, lp;
            split_pack(v0, v1, hp, lp);
            hHi[r0 * HSTR + cp] = hp; hLo[r0 * HSTR + cp] = lp;
            split_pack(v2, v3, hp, lp);
            hHi[(r0 + 8) * HSTR + cp] = hp; hLo[(r0 + 8) * HSTR + cp] = lp;
        }
    }

    // stage W3T rows 0..7 (first 8 out cols), full K=256, into B region
    if (t < 64) {
        int n = t >> 3, i = (t & 7) * 16;   // b32 offset within 128-word row
        const uint4* sh = (const uint4*)(w3h + (size_t)n * H_DIM + i * 2);
        const uint4* sl = (const uint4*)(w3l + (size_t)n * H_DIM + i * 2);
        #pragma unroll
        for (int j = 0; j < 4; j++) {
            *(uint4*)&bHi[n * HSTR + i + j * 4] = sh[j];
            *(uint4*)&bLo[n * HSTR + i + j * 4] = sl[j];
        }
    }
    __syncthreads();

    // =================== Layer 3: y = h2 @ W3[:, :8] + b3 (warps 0..7) ===================
    if (wid < 8) {
        float acc3[4] = {0.f, 0.f, 0.f, 0.f};
        const uint32_t* pAh = hHi + wid * 16 * HSTR;
        const uint32_t* pAl = hLo + wid * 16 * HSTR;
        #pragma unroll
        for (int ks = 0; ks < 16; ks++) {
            const int kb = ks * 8 + tig;
            uint32_t ah[4], al[4];
            ah[0] = pAh[gid * HSTR + kb];       ah[1] = pAh[(gid + 8) * HSTR + kb];
            ah[2] = pAh[gid * HSTR + kb + 4];   ah[3] = pAh[(gid + 8) * HSTR + kb + 4];
            al[0] = pAl[gid * HSTR + kb];       al[1] = pAl[(gid + 8) * HSTR + kb];
            al[2] = pAl[gid * HSTR + kb + 4];   al[3] = pAl[(gid + 8) * HSTR + kb + 4];
            uint32_t bh[2] = { bHi[gid * HSTR + kb], bHi[gid * HSTR + kb + 4] };
            uint32_t bl[2] = { bLo[gid * HSTR + kb], bLo[gid * HSTR + kb + 4] };
            mma16816(acc3, ah, bh);
            mma16816(acc3, ah, bl);
            mma16816(acc3, al, bh);
        }
        int r0 = wid * 16 + gid;
        int c  = 2 * tig;
        if (r0 < nrows) {
            float* o = out + (size_t)sIdx[r0] * DA + c;
            o[0] = acc3[0] + sB3[c];
            o[1] = acc3[1] + sB3[c + 1];
        }
        if (r0 + 8 < nrows) {
            float* o = out + (size_t)sIdx[r0 + 8] * DA + c;
            o[0] = acc3[2] + sB3[c];
            o[1] = acc3[3] + sB3[c + 1];
        }
    }
}

extern "C" void kernel_launch(void* const* d_in, const int* in_sizes, int n_in,
                              void* d_out, int out_size)
{
    const float* features = (const float*)d_in[0];
    const float* W1 = (const float*)d_in[1];
    const float* b1 = (const float*)d_in[2];
    const float* W2 = (const float*)d_in[3];
    const float* b2 = (const float*)d_in[4];
    const float* W3 = (const float*)d_in[5];
    const float* b3 = (const float*)d_in[6];
    const int*   ma = (const int*)d_in[7];
    float* out = (float*)d_out;

    cudaFuncSetAttribute(moe_mma_kernel, cudaFuncAttributeMaxDynamicSharedMemorySize,
                         SMEM_WORDS * 4);

    zero_counts_kernel<<<1, 32>>>();
    scatter_kernel<<<B_ROWS / 256, 256>>>(ma);
    prep_weights<<<dim3(128, E_NUM, 3), dim3(32, 8)>>>(W1, W2, W3);
    moe_mma_kernel<<<dim3(NTILES, E_NUM), 512, SMEM_WORDS * 4>>>(features, b1, b2, b3, out);
}

// round 7
// speedup vs baseline: 3.2528x; 1.0184x over previous
#include <cuda_runtime.h>
#include <cuda_bf16.h>
#include <cstdint>

#define B_ROWS 16384
#define F_DIM  512
#define H_DIM  256
#define E_NUM  8
#define OUT_DIM 32
#define DA     8
#define TM     128
#define NTILES (B_ROWS / TM)   // 128

#define ASTR 36    // b32 stride, 64-bf16 rows (32 words + 4 pad)
#define B2STR 20   // b32 stride, 32-bf16 rows (16 words + 4 pad)
#define HSTR 132   // b32 stride, 256-bf16 h rows (128 words + 4 pad)

// ---------------- device scratch ----------------
__device__ int g_counts[E_NUM];
__device__ int g_bucket[E_NUM][B_ROWS];

__device__ __align__(16) __nv_bfloat16 g_W1T_hi[E_NUM][H_DIM][F_DIM];
__device__ __align__(16) __nv_bfloat16 g_W1T_lo[E_NUM][H_DIM][F_DIM];
__device__ __align__(16) __nv_bfloat16 g_W2T_hi[E_NUM][H_DIM][H_DIM];
__device__ __align__(16) __nv_bfloat16 g_W2T_lo[E_NUM][H_DIM][H_DIM];
__device__ __align__(16) __nv_bfloat16 g_W3T_hi[E_NUM][OUT_DIM][H_DIM];
__device__ __align__(16) __nv_bfloat16 g_W3T_lo[E_NUM][OUT_DIM][H_DIM];

__device__ __forceinline__ void split1(float x, __nv_bfloat16& h, __nv_bfloat16& l) {
    h = __float2bfloat16_rn(x);
    l = __float2bfloat16_rn(x - __bfloat162float(h));
}
__device__ __forceinline__ uint32_t packbf(__nv_bfloat16 a, __nv_bfloat16 b) {
    __nv_bfloat162 t(a, b);
    return *reinterpret_cast<uint32_t*>(&t);
}
__device__ __forceinline__ void split_pack(float v0, float v1, uint32_t& hp, uint32_t& lp) {
    __nv_bfloat16 h0, l0, h1, l1;
    split1(v0, h0, l0); split1(v1, h1, l1);
    hp = packbf(h0, h1);
    lp = packbf(l0, l1);
}
__device__ __forceinline__ uint32_t smem_u32(const void* p) {
    uint32_t a;
    asm("{ .reg .u64 t; cvta.to.shared.u64 t, %1; cvt.u32.u64 %0, t; }" : "=r"(a) : "l"(p));
    return a;
}
__device__ __forceinline__ void cpasync16(uint32_t dst, const void* src) {
    asm volatile("cp.async.cg.shared.global [%0], [%1], 16;" :: "r"(dst), "l"(src));
}
#define CP_COMMIT() asm volatile("cp.async.commit_group;")
#define CP_WAIT0()  asm volatile("cp.async.wait_group 0;")

__device__ __forceinline__ void mma16816(float* d, const uint32_t* a, const uint32_t* b) {
    asm volatile("mma.sync.aligned.m16n8k16.row.col.f32.bf16.bf16.f32 "
        "{%0,%1,%2,%3}, {%4,%5,%6,%7}, {%8,%9}, {%0,%1,%2,%3};"
        : "+f"(d[0]), "+f"(d[1]), "+f"(d[2]), "+f"(d[3])
        : "r"(a[0]), "r"(a[1]), "r"(a[2]), "r"(a[3]), "r"(b[0]), "r"(b[1]));
}

// Warp-tile (32 rows x 64 cols) over NKS*16 K, bf16x3 split.
template<int LDA, int LDB, int NKS>
__device__ __forceinline__ void mma_chunk(
    float acc[2][8][4],
    const uint32_t* __restrict__ aHi, const uint32_t* __restrict__ aLo,
    const uint32_t* __restrict__ bHi, const uint32_t* __restrict__ bLo,
    int gid, int tig)
{
    #pragma unroll
    for (int ks = 0; ks < NKS; ks++) {
        const int kb = ks * 8 + tig;
        uint32_t ah[2][4], al[2][4];
        #pragma unroll
        for (int mi = 0; mi < 2; mi++) {
            const uint32_t* pH = aHi + (mi * 16 + gid) * LDA + kb;
            const uint32_t* pL = aLo + (mi * 16 + gid) * LDA + kb;
            ah[mi][0] = pH[0]; ah[mi][1] = pH[8 * LDA]; ah[mi][2] = pH[4]; ah[mi][3] = pH[8 * LDA + 4];
            al[mi][0] = pL[0]; al[mi][1] = pL[8 * LDA]; al[mi][2] = pL[4]; al[mi][3] = pL[8 * LDA + 4];
        }
        #pragma unroll
        for (int ni = 0; ni < 8; ni++) {
            const uint32_t* qH = bHi + (ni * 8 + gid) * LDB + kb;
            const uint32_t* qL = bLo + (ni * 8 + gid) * LDB + kb;
            uint32_t bh[2] = { qH[0], qH[4] };
            uint32_t bl[2] = { qL[0], qL[4] };
            #pragma unroll
            for (int mi = 0; mi < 2; mi++) {
                mma16816(acc[mi][ni], ah[mi], bh);
                mma16816(acc[mi][ni], ah[mi], bl);
                mma16816(acc[mi][ni], al[mi], bh);
            }
        }
    }
}

// ---------------- prep kernels ----------------
__global__ void zero_counts_kernel() {
    if (threadIdx.x < E_NUM) g_counts[threadIdx.x] = 0;
}
__global__ void scatter_kernel(const int* __restrict__ ma) {
    int i = blockIdx.x * blockDim.x + threadIdx.x;
    if (i < B_ROWS) {
        int e = ma[i];
        int p = atomicAdd(&g_counts[e], 1);
        g_bucket[e][p] = i;
    }
}
__global__ void prep_weights(const float* __restrict__ W1,
                             const float* __restrict__ W2,
                             const float* __restrict__ W3) {
    int z = blockIdx.z, e = blockIdx.y;
    int Kd = (z == 0) ? F_DIM : H_DIM;
    int Nd = (z == 0) ? H_DIM : ((z == 1) ? H_DIM : OUT_DIM);
    int ntn = Nd / 32;
    int tk = (blockIdx.x / ntn) * 32;
    int tn = (blockIdx.x % ntn) * 32;
    if (tk >= Kd) return;
    const float* src = ((z == 0) ? W1 : (z == 1) ? W2 : W3) + (size_t)e * Kd * Nd;
    __nv_bfloat16* dh = (z == 0) ? &g_W1T_hi[e][0][0] : (z == 1) ? &g_W2T_hi[e][0][0] : &g_W3T_hi[e][0][0];
    __nv_bfloat16* dl = (z == 0) ? &g_W1T_lo[e][0][0] : (z == 1) ? &g_W2T_lo[e][0][0] : &g_W3T_lo[e][0][0];
    __shared__ float tile[32][33];
    int tx = threadIdx.x, ty = threadIdx.y;   // 32 x 8
    #pragma unroll
    for (int r = 0; r < 4; r++)
        tile[ty + r * 8][tx] = src[(size_t)(tk + ty + r * 8) * Nd + tn + tx];
    __syncthreads();
    #pragma unroll
    for (int r = 0; r < 4; r++) {
        int n = tn + ty + r * 8, k = tk + tx;
        float v = tile[tx][ty + r * 8];
        __nv_bfloat16 h, l; split1(v, h, l);
        dh[(size_t)n * Kd + k] = h;
        dl[(size_t)n * Kd + k] = l;
    }
}

// ---------------- smem layout (b32 words) ----------------
// Layer 1: B1 double (2 x 18432: hi 9216 + lo 9216) + A double (2 x 9216: hi 4608 + lo 4608)
// Layers 2+: h (hi 16896 + lo 16896, aliases B1) + B2 double (2 x 10240, aliases A)
#define B1_HI(b) ((b) * 18432)
#define B1_LO(b) (B1_HI(b) + 9216)
#define A_HI(b)  (36864 + (b) * 9216)
#define A_LO(b)  (A_HI(b) + 4608)
#define OFF_HHI  0
#define OFF_HLO  16896
#define B2_HI(b) (36864 + (b) * 10240)
#define B2_LO(b) (B2_HI(b) + 5120)
#define OFF_W3HI 36864
#define OFF_W3LO (36864 + 1056)
#define OFF_IDX  57344
#define OFF_SB1  57472
#define OFF_SB2  57728
#define OFF_SB3  57984
#define SMEM_WORDS 57992     // 231968 bytes

// ---------------- main MMA kernel: 512 threads, 4x4 warps ----------------
__global__ __launch_bounds__(512, 1)
void moe_mma_kernel(const float* __restrict__ features,
                    const float* __restrict__ b1,
                    const float* __restrict__ b2,
                    const float* __restrict__ b3,
                    float* __restrict__ out)
{
    const int e = blockIdx.y;
    const int count = g_counts[e];
    const int row0 = blockIdx.x * TM;
    if (row0 >= count) return;
    const int nrows = min(TM, count - row0);

    extern __shared__ uint32_t sm[];
    const uint32_t sb = smem_u32(sm);
    int*   sIdx = (int*)(sm + OFF_IDX);
    float* sB1  = (float*)(sm + OFF_SB1);
    float* sB2  = (float*)(sm + OFF_SB2);
    float* sB3  = (float*)(sm + OFF_SB3);
    uint32_t* hHi = sm + OFF_HHI;
    uint32_t* hLo = sm + OFF_HLO;

    const int t    = threadIdx.x;
    const int wid  = t >> 5;
    const int lane = t & 31;
    const int gid  = lane >> 2;
    const int tig  = lane & 3;
    const int wrow = wid & 3;       // 4 row-warps * 32 rows
    const int wcol = wid >> 2;      // 4 col-warps * 64 cols

    if (t < TM) sIdx[t] = g_bucket[e][row0 + min(t, nrows - 1)];
    if (t < H_DIM) {
        sB1[t] = b1[e * H_DIM + t];
        sB2[t] = b2[e * H_DIM + t];
    }
    if (t < DA) sB3[t] = b3[e * OUT_DIM + t];
    __syncthreads();

    // staging roles
    const int arow = t >> 2, aseg = t & 3;     // A: 128 rows x 4 segs of 16 floats
    const int brow = t >> 1, bhalf = t & 1;    // B: 256 rows x 2 halves
    const float* frow = features + (size_t)sIdx[arow] * F_DIM;

    const __nv_bfloat16* w1h = &g_W1T_hi[e][0][0];
    const __nv_bfloat16* w1l = &g_W1T_lo[e][0][0];
    const __nv_bfloat16* w2h = &g_W2T_hi[e][0][0];
    const __nv_bfloat16* w2l = &g_W2T_lo[e][0][0];
    const __nv_bfloat16* w3h = &g_W3T_hi[e][0][0];
    const __nv_bfloat16* w3l = &g_W3T_lo[e][0][0];

    float acc[2][8][4];
    #pragma unroll
    for (int mi = 0; mi < 2; mi++)
        #pragma unroll
        for (int ni = 0; ni < 8; ni++)
            #pragma unroll
            for (int c = 0; c < 4; c++) acc[mi][ni][c] = 0.f;

    // helper lambdas (inlined)
    auto issueB1 = [&](int kc, int buf) {
        const __nv_bfloat16* sh = w1h + (size_t)brow * F_DIM + kc * 64 + bhalf * 32;
        const __nv_bfloat16* sl = w1l + (size_t)brow * F_DIM + kc * 64 + bhalf * 32;
        uint32_t dh = sb + (B1_HI(buf) + brow * ASTR + bhalf * 16) * 4;
        uint32_t dl = sb + (B1_LO(buf) + brow * ASTR + bhalf * 16) * 4;
        #pragma unroll
        for (int c = 0; c < 4; c++) {
            cpasync16(dh + c * 16, sh + c * 8);
            cpasync16(dl + c * 16, sl + c * 8);
        }
        CP_COMMIT();
    };
    auto stageA = [&](const float4* v4, int buf) {
        uint32_t* dH = sm + A_HI(buf) + arow * ASTR + aseg * 8;
        uint32_t* dL = sm + A_LO(buf) + arow * ASTR + aseg * 8;
        #pragma unroll
        for (int j = 0; j < 4; j++) {
            uint32_t h0, l0, h1, l1;
            split_pack(v4[j].x, v4[j].y, h0, l0);
            split_pack(v4[j].z, v4[j].w, h1, l1);
            dH[j * 2] = h0; dH[j * 2 + 1] = h1;
            dL[j * 2] = l0; dL[j * 2 + 1] = l1;
        }
    };
    auto issueB2 = [&](int kc, int buf) {
        const __nv_bfloat16* sh = w2h + (size_t)brow * H_DIM + kc * 32 + bhalf * 16;
        const __nv_bfloat16* sl = w2l + (size_t)brow * H_DIM + kc * 32 + bhalf * 16;
        uint32_t dh = sb + (B2_HI(buf) + brow * B2STR + bhalf * 8) * 4;
        uint32_t dl = sb + (B2_LO(buf) + brow * B2STR + bhalf * 8) * 4;
        #pragma unroll
        for (int c = 0; c < 2; c++) {
            cpasync16(dh + c * 16, sh + c * 8);
            cpasync16(dl + c * 16, sl + c * 8);
        }
        CP_COMMIT();
    };

    // ============ Layer 1 pipeline: 8 chunks of K=64 ============
    {
        // prologue: chunk 0 in flight
        issueB1(0, 0);
        {
            float4 v4[4];
            const float* src = frow + aseg * 16;
            #pragma unroll
            for (int j = 0; j < 4; j++) v4[j] = *(const float4*)(src + j * 4);
            stageA(v4, 0);
        }
        #pragma unroll 1
        for (int kc = 0; kc < 8; kc++) {
            const int cur = kc & 1, nxt = cur ^ 1;
            CP_WAIT0();
            __syncthreads();   // chunk kc visible; all warps done with MMA kc-1
            float4 v4[4];
            if (kc < 7) {
                issueB1(kc + 1, nxt);
                const float* src = frow + (kc + 1) * 64 + aseg * 16;
                #pragma unroll
                for (int j = 0; j < 4; j++) v4[j] = *(const float4*)(src + j * 4);
            }
            mma_chunk<ASTR, ASTR, 4>(acc,
                sm + A_HI(cur) + wrow * 32 * ASTR,
                sm + A_LO(cur) + wrow * 32 * ASTR,
                sm + B1_HI(cur) + wcol * 64 * ASTR,
                sm + B1_LO(cur) + wcol * 64 * ASTR,
                gid, tig);
            if (kc < 7) stageA(v4, nxt);
        }
    }
    __syncthreads();   // all layer-1 MMA done: safe to write h (aliases B1) & B2 prologue (aliases A)

    issueB2(0, 0);     // layer-2 prologue overlaps epilogue 1

    // epilogue 1: relu + bias -> h
    #pragma unroll
    for (int mi = 0; mi < 2; mi++) {
        int r0 = wrow * 32 + mi * 16 + gid;
        #pragma unroll
        for (int ni = 0; ni < 8; ni++) {
            int col = wcol * 64 + ni * 8 + 2 * tig;
            int cp  = col >> 1;
            float v0 = fmaxf(acc[mi][ni][0] + sB1[col], 0.f);
            float v1 = fmaxf(acc[mi][ni][1] + sB1[col + 1], 0.f);
            float v2 = fmaxf(acc[mi][ni][2] + sB1[col], 0.f);
            float v3 = fmaxf(acc[mi][ni][3] + sB1[col + 1], 0.f);
            uint32_t hp, lp;
            split_pack(v0, v1, hp, lp);
            hHi[r0 * HSTR + cp] = hp; hLo[r0 * HSTR + cp] = lp;
            split_pack(v2, v3, hp, lp);
            hHi[(r0 + 8) * HSTR + cp] = hp; hLo[(r0 + 8) * HSTR + cp] = lp;
            acc[mi][ni][0] = 0.f; acc[mi][ni][1] = 0.f;
            acc[mi][ni][2] = 0.f; acc[mi][ni][3] = 0.f;
        }
    }

    // ============ Layer 2 pipeline: 8 chunks of K=32 ============
    #pragma unroll 1
    for (int kc = 0; kc < 8; kc++) {
        const int cur = kc & 1, nxt = cur ^ 1;
        CP_WAIT0();
        __syncthreads();   // chunk kc + h (kc==0) visible; MMA kc-1 done
        if (kc < 7) issueB2(kc + 1, nxt);
        mma_chunk<HSTR, B2STR, 2>(acc,
            hHi + wrow * 32 * HSTR + kc * 16,
            hLo + wrow * 32 * HSTR + kc * 16,
            sm + B2_HI(cur) + wcol * 64 * B2STR,
            sm + B2_LO(cur) + wcol * 64 * B2STR,
            gid, tig);
    }
    __syncthreads();   // all layer-2 MMA done: safe to overwrite h and B2 region (W3)

    // stage W3T rows 0..7 (first 8 out cols), K=256
    if (t < 64) {
        int n = t >> 3, i = (t & 7) * 16;
        const uint4* sh = (const uint4*)(w3h + (size_t)n * H_DIM + i * 2);
        const uint4* sl = (const uint4*)(w3l + (size_t)n * H_DIM + i * 2);
        #pragma unroll
        for (int j = 0; j < 4; j++) {
            *(uint4*)&sm[OFF_W3HI + n * HSTR + i + j * 4] = sh[j];
            *(uint4*)&sm[OFF_W3LO + n * HSTR + i + j * 4] = sl[j];
        }
    }

    // epilogue 2: relu + bias -> h (overwrite)
    #pragma unroll
    for (int mi = 0; mi < 2; mi++) {
        int r0 = wrow * 32 + mi * 16 + gid;
        #pragma unroll
        for (int ni = 0; ni < 8; ni++) {
            int col = wcol * 64 + ni * 8 + 2 * tig;
            int cp  = col >> 1;
            float v0 = fmaxf(acc[mi][ni][0] + sB2[col], 0.f);
            float v1 = fmaxf(acc[mi][ni][1] + sB2[col + 1], 0.f);
            float v2 = fmaxf(acc[mi][ni][2] + sB2[col], 0.f);
            float v3 = fmaxf(acc[mi][ni][3] + sB2[col + 1], 0.f);
            uint32_t hp, lp;
            split_pack(v0, v1, hp, lp);
            hHi[r0 * HSTR + cp] = hp; hLo[r0 * HSTR + cp] = lp;
            split_pack(v2, v3, hp, lp);
            hHi[(r0 + 8) * HSTR + cp] = hp; hLo[(r0 + 8) * HSTR + cp] = lp;
        }
    }
    __syncthreads();

    // ============ Layer 3: y = h2 @ W3[:, :8] + b3 (warps 0..7) ============
    if (wid < 8) {
        float acc3[4] = {0.f, 0.f, 0.f, 0.f};
        const uint32_t* pAh = hHi + wid * 16 * HSTR;
        const uint32_t* pAl = hLo + wid * 16 * HSTR;
        const uint32_t* w3H = sm + OFF_W3HI;
        const uint32_t* w3L = sm + OFF_W3LO;
        #pragma unroll
        for (int ks = 0; ks < 16; ks++) {
            const int kb = ks * 8 + tig;
            uint32_t ah[4], al[4];
            ah[0] = pAh[gid * HSTR + kb];       ah[1] = pAh[(gid + 8) * HSTR + kb];
            ah[2] = pAh[gid * HSTR + kb + 4];   ah[3] = pAh[(gid + 8) * HSTR + kb + 4];
            al[0] = pAl[gid * HSTR + kb];       al[1] = pAl[(gid + 8) * HSTR + kb];
            al[2] = pAl[gid * HSTR + kb + 4];   al[3] = pAl[(gid + 8) * HSTR + kb + 4];
            uint32_t bh[2] = { w3H[gid * HSTR + kb], w3H[gid * HSTR + kb + 4] };
            uint32_t bl[2] = { w3L[gid * HSTR + kb], w3L[gid * HSTR + kb + 4] };
            mma16816(acc3, ah, bh);
            mma16816(acc3, ah, bl);
            mma16816(acc3, al, bh);
        }
        int r0 = wid * 16 + gid;
        int c  = 2 * tig;
        if (r0 < nrows) {
            float* o = out + (size_t)sIdx[r0] * DA + c;
            o[0] = acc3[0] + sB3[c];
            o[1] = acc3[1] + sB3[c + 1];
        }
        if (r0 + 8 < nrows) {
            float* o = out + (size_t)sIdx[r0 + 8] * DA + c;
            o[0] = acc3[2] + sB3[c];
            o[1] = acc3[3] + sB3[c + 1];
        }
    }
}

extern "C" void kernel_launch(void* const* d_in, const int* in_sizes, int n_in,
                              void* d_out, int out_size)
{
    const float* features = (const float*)d_in[0];
    const float* W1 = (const float*)d_in[1];
    const float* b1 = (const float*)d_in[2];
    const float* W2 = (const float*)d_in[3];
    const float* b2 = (const float*)d_in[4];
    const float* W3 = (const float*)d_in[5];
    const float* b3 = (const float*)d_in[6];
    const int*   ma = (const int*)d_in[7];
    float* out = (float*)d_out;

    cudaFuncSetAttribute(moe_mma_kernel, cudaFuncAttributeMaxDynamicSharedMemorySize,
                         SMEM_WORDS * 4);

    zero_counts_kernel<<<1, 32>>>();
    scatter_kernel<<<B_ROWS / 256, 256>>>(ma);
    prep_weights<<<dim3(128, E_NUM, 3), dim3(32, 8)>>>(W1, W2, W3);
    moe_mma_kernel<<<dim3(NTILES, E_NUM), 512, SMEM_WORDS * 4>>>(features, b1, b2, b3, out);
}

// round 8
// speedup vs baseline: 3.5674x; 1.0967x over previous
#include <cuda_runtime.h>
#include <cuda_bf16.h>
#include <cstdint>

#define B_ROWS 16384
#define F_DIM  512
#define H_DIM  256
#define E_NUM  8
#define OUT_DIM 32
#define DA     8
#define TM     128
#define NTILES (B_ROWS / TM)   // 128

#define ASTR 36    // b32 stride, 64-bf16 rows (32 words + 4 pad)
#define B2STR 20   // b32 stride, 32-bf16 rows (16 words + 4 pad)
#define HSTR 132   // b32 stride, 256-bf16 h rows (128 words + 4 pad)

// ---------------- device scratch ----------------
__device__ int g_counts[E_NUM];
__device__ int g_bucket[E_NUM][B_ROWS];

__device__ __align__(16) __nv_bfloat16 g_W1T_hi[E_NUM][H_DIM][F_DIM];
__device__ __align__(16) __nv_bfloat16 g_W1T_lo[E_NUM][H_DIM][F_DIM];
__device__ __align__(16) __nv_bfloat16 g_W2T_hi[E_NUM][H_DIM][H_DIM];
__device__ __align__(16) __nv_bfloat16 g_W2T_lo[E_NUM][H_DIM][H_DIM];
__device__ __align__(16) __nv_bfloat16 g_W3T_hi[E_NUM][OUT_DIM][H_DIM];
__device__ __align__(16) __nv_bfloat16 g_W3T_lo[E_NUM][OUT_DIM][H_DIM];

__device__ __forceinline__ void split1(float x, __nv_bfloat16& h, __nv_bfloat16& l) {
    h = __float2bfloat16_rn(x);
    l = __float2bfloat16_rn(x - __bfloat162float(h));
}
__device__ __forceinline__ uint32_t packbf(__nv_bfloat16 a, __nv_bfloat16 b) {
    __nv_bfloat162 t(a, b);
    return *reinterpret_cast<uint32_t*>(&t);
}
__device__ __forceinline__ void split_pack(float v0, float v1, uint32_t& hp, uint32_t& lp) {
    __nv_bfloat16 h0, l0, h1, l1;
    split1(v0, h0, l0); split1(v1, h1, l1);
    hp = packbf(h0, h1);
    lp = packbf(l0, l1);
}
__device__ __forceinline__ uint32_t smem_u32(const void* p) {
    uint32_t a;
    asm("{ .reg .u64 t; cvta.to.shared.u64 t, %1; cvt.u32.u64 %0, t; }" : "=r"(a) : "l"(p));
    return a;
}
__device__ __forceinline__ void cpasync16(uint32_t dst, const void* src) {
    asm volatile("cp.async.cg.shared.global [%0], [%1], 16;" :: "r"(dst), "l"(src));
}
#define CP_COMMIT() asm volatile("cp.async.commit_group;")
#define CP_WAIT0()  asm volatile("cp.async.wait_group 0;")

__device__ __forceinline__ void mma16816(float* d, const uint32_t* a, const uint32_t* b) {
    asm volatile("mma.sync.aligned.m16n8k16.row.col.f32.bf16.bf16.f32 "
        "{%0,%1,%2,%3}, {%4,%5,%6,%7}, {%8,%9}, {%0,%1,%2,%3};"
        : "+f"(d[0]), "+f"(d[1]), "+f"(d[2]), "+f"(d[3])
        : "r"(a[0]), "r"(a[1]), "r"(a[2]), "r"(a[3]), "r"(b[0]), "r"(b[1]));
}
__device__ __forceinline__ void ldsm_x4(uint32_t* r, uint32_t addr) {
    asm volatile("ldmatrix.sync.aligned.m8n8.x4.shared.b16 {%0,%1,%2,%3}, [%4];"
        : "=r"(r[0]), "=r"(r[1]), "=r"(r[2]), "=r"(r[3]) : "r"(addr));
}

// Warp-tile (32 rows x 64 cols) over NKS*16 K, bf16x3 split, ldmatrix frags.
// aHi/aLo/bHi/bLo: warp+lane-adjusted smem BYTE addresses at ks=0, mi=0 / p=0.
template<int LDA, int LDB, int NKS>
__device__ __forceinline__ void mma_chunk_ldsm(
    float acc[2][8][4],
    uint32_t aHi, uint32_t aLo, uint32_t bHi, uint32_t bLo)
{
    #pragma unroll
    for (int ks = 0; ks < NKS; ks++) {
        uint32_t ah[2][4], al[2][4];
        #pragma unroll
        for (int mi = 0; mi < 2; mi++) {
            ldsm_x4(ah[mi], aHi + mi * (16 * LDA * 4) + ks * 32);
            ldsm_x4(al[mi], aLo + mi * (16 * LDA * 4) + ks * 32);
        }
        #pragma unroll
        for (int p = 0; p < 4; p++) {
            uint32_t bh[4], bl[4];
            ldsm_x4(bh, bHi + p * (16 * LDB * 4) + ks * 32);
            ldsm_x4(bl, bLo + p * (16 * LDB * 4) + ks * 32);
            #pragma unroll
            for (int q = 0; q < 2; q++) {
                const int ni = p * 2 + q;
                #pragma unroll
                for (int mi = 0; mi < 2; mi++) {
                    mma16816(acc[mi][ni], ah[mi], bh + q * 2);
                    mma16816(acc[mi][ni], ah[mi], bl + q * 2);
                    mma16816(acc[mi][ni], al[mi], bh + q * 2);
                }
            }
        }
    }
}

// ---------------- prep kernels ----------------
__global__ void zero_counts_kernel() {
    if (threadIdx.x < E_NUM) g_counts[threadIdx.x] = 0;
}
__global__ void scatter_kernel(const int* __restrict__ ma) {
    int i = blockIdx.x * blockDim.x + threadIdx.x;
    if (i < B_ROWS) {
        int e = ma[i];
        int p = atomicAdd(&g_counts[e], 1);
        g_bucket[e][p] = i;
    }
}
__global__ void prep_weights(const float* __restrict__ W1,
                             const float* __restrict__ W2,
                             const float* __restrict__ W3) {
    int z = blockIdx.z, e = blockIdx.y;
    int Kd = (z == 0) ? F_DIM : H_DIM;
    int Nd = (z == 0) ? H_DIM : ((z == 1) ? H_DIM : OUT_DIM);
    int ntn = Nd / 32;
    int tk = (blockIdx.x / ntn) * 32;
    int tn = (blockIdx.x % ntn) * 32;
    if (tk >= Kd) return;
    const float* src = ((z == 0) ? W1 : (z == 1) ? W2 : W3) + (size_t)e * Kd * Nd;
    __nv_bfloat16* dh = (z == 0) ? &g_W1T_hi[e][0][0] : (z == 1) ? &g_W2T_hi[e][0][0] : &g_W3T_hi[e][0][0];
    __nv_bfloat16* dl = (z == 0) ? &g_W1T_lo[e][0][0] : (z == 1) ? &g_W2T_lo[e][0][0] : &g_W3T_lo[e][0][0];
    __shared__ float tile[32][33];
    int tx = threadIdx.x, ty = threadIdx.y;   // 32 x 8
    #pragma unroll
    for (int r = 0; r < 4; r++)
        tile[ty + r * 8][tx] = src[(size_t)(tk + ty + r * 8) * Nd + tn + tx];
    __syncthreads();
    #pragma unroll
    for (int r = 0; r < 4; r++) {
        int n = tn + ty + r * 8, k = tk + tx;
        float v = tile[tx][ty + r * 8];
        __nv_bfloat16 h, l; split1(v, h, l);
        dh[(size_t)n * Kd + k] = h;
        dl[(size_t)n * Kd + k] = l;
    }
}

// ---------------- smem layout (b32 words) ----------------
#define B1_HI(b) ((b) * 18432)
#define B1_LO(b) (B1_HI(b) + 9216)
#define A_HI(b)  (36864 + (b) * 9216)
#define A_LO(b)  (A_HI(b) + 4608)
#define OFF_HHI  0
#define OFF_HLO  16896
#define B2_HI(b) (36864 + (b) * 10240)
#define B2_LO(b) (B2_HI(b) + 5120)
#define OFF_W3HI 36864
#define OFF_W3LO (36864 + 1056)
#define OFF_IDX  57344
#define OFF_SB1  57472
#define OFF_SB2  57728
#define OFF_SB3  57984
#define SMEM_WORDS 57992     // 231968 bytes

// ---------------- main MMA kernel: 512 threads, 4x4 warps ----------------
__global__ __launch_bounds__(512, 1)
void moe_mma_kernel(const float* __restrict__ features,
                    const float* __restrict__ b1,
                    const float* __restrict__ b2,
                    const float* __restrict__ b3,
                    float* __restrict__ out)
{
    const int e = blockIdx.y;
    const int count = g_counts[e];
    const int row0 = blockIdx.x * TM;
    if (row0 >= count) return;
    const int nrows = min(TM, count - row0);

    extern __shared__ uint32_t sm[];
    const uint32_t sb = smem_u32(sm);
    int*   sIdx = (int*)(sm + OFF_IDX);
    float* sB1  = (float*)(sm + OFF_SB1);
    float* sB2  = (float*)(sm + OFF_SB2);
    float* sB3  = (float*)(sm + OFF_SB3);
    uint32_t* hHi = sm + OFF_HHI;
    uint32_t* hLo = sm + OFF_HLO;

    const int t    = threadIdx.x;
    const int wid  = t >> 5;
    const int lane = t & 31;
    const int gid  = lane >> 2;
    const int tig  = lane & 3;
    const int wrow = wid & 3;       // 4 row-warps * 32 rows
    const int wcol = wid >> 2;      // 4 col-warps * 64 cols

    // ldmatrix per-lane byte offsets
    const int l8 = lane & 7, lq = lane >> 3;
    const int laneA_A  = ((l8 + 8 * (lq & 1)) * ASTR)  * 4 + (lq >> 1) * 16;
    const int laneA_H  = ((l8 + 8 * (lq & 1)) * HSTR)  * 4 + (lq >> 1) * 16;
    const int laneB_A  = ((l8 + 8 * (lq >> 1)) * ASTR) * 4 + (lq & 1) * 16;
    const int laneB_B2 = ((l8 + 8 * (lq >> 1)) * B2STR) * 4 + (lq & 1) * 16;

    if (t < TM) sIdx[t] = g_bucket[e][row0 + min(t, nrows - 1)];
    if (t < H_DIM) {
        sB1[t] = b1[e * H_DIM + t];
        sB2[t] = b2[e * H_DIM + t];
    }
    if (t < DA) sB3[t] = b3[e * OUT_DIM + t];
    __syncthreads();

    // staging roles
    const int arow = t >> 2, aseg = t & 3;     // A: 128 rows x 4 segs of 16 floats
    const int brow = t >> 1, bhalf = t & 1;    // B: 256 rows x 2 halves
    const float* frow = features + (size_t)sIdx[arow] * F_DIM;

    const __nv_bfloat16* w1h = &g_W1T_hi[e][0][0];
    const __nv_bfloat16* w1l = &g_W1T_lo[e][0][0];
    const __nv_bfloat16* w2h = &g_W2T_hi[e][0][0];
    const __nv_bfloat16* w2l = &g_W2T_lo[e][0][0];
    const __nv_bfloat16* w3h = &g_W3T_hi[e][0][0];
    const __nv_bfloat16* w3l = &g_W3T_lo[e][0][0];

    float acc[2][8][4];
    #pragma unroll
    for (int mi = 0; mi < 2; mi++)
        #pragma unroll
        for (int ni = 0; ni < 8; ni++)
            #pragma unroll
            for (int c = 0; c < 4; c++) acc[mi][ni][c] = 0.f;

    auto issueB1 = [&](int kc, int buf) {
        const __nv_bfloat16* sh = w1h + (size_t)brow * F_DIM + kc * 64 + bhalf * 32;
        const __nv_bfloat16* sl = w1l + (size_t)brow * F_DIM + kc * 64 + bhalf * 32;
        uint32_t dh = sb + (B1_HI(buf) + brow * ASTR + bhalf * 16) * 4;
        uint32_t dl = sb + (B1_LO(buf) + brow * ASTR + bhalf * 16) * 4;
        #pragma unroll
        for (int c = 0; c < 4; c++) {
            cpasync16(dh + c * 16, sh + c * 8);
            cpasync16(dl + c * 16, sl + c * 8);
        }
        CP_COMMIT();
    };
    auto stageA = [&](const float4* v4, int buf) {
        uint32_t* dH = sm + A_HI(buf) + arow * ASTR + aseg * 8;
        uint32_t* dL = sm + A_LO(buf) + arow * ASTR + aseg * 8;
        #pragma unroll
        for (int j = 0; j < 4; j++) {
            uint32_t h0, l0, h1, l1;
            split_pack(v4[j].x, v4[j].y, h0, l0);
            split_pack(v4[j].z, v4[j].w, h1, l1);
            dH[j * 2] = h0; dH[j * 2 + 1] = h1;
            dL[j * 2] = l0; dL[j * 2 + 1] = l1;
        }
    };
    auto issueB2 = [&](int kc, int buf) {
        const __nv_bfloat16* sh = w2h + (size_t)brow * H_DIM + kc * 32 + bhalf * 16;
        const __nv_bfloat16* sl = w2l + (size_t)brow * H_DIM + kc * 32 + bhalf * 16;
        uint32_t dh = sb + (B2_HI(buf) + brow * B2STR + bhalf * 8) * 4;
        uint32_t dl = sb + (B2_LO(buf) + brow * B2STR + bhalf * 8) * 4;
        #pragma unroll
        for (int c = 0; c < 2; c++) {
            cpasync16(dh + c * 16, sh + c * 8);
            cpasync16(dl + c * 16, sl + c * 8);
        }
        CP_COMMIT();
    };

    // ============ Layer 1 pipeline: 8 chunks of K=64 ============
    {
        issueB1(0, 0);
        {
            float4 v4[4];
            const float* src = frow + aseg * 16;
            #pragma unroll
            for (int j = 0; j < 4; j++) v4[j] = *(const float4*)(src + j * 4);
            stageA(v4, 0);
        }
        #pragma unroll 1
        for (int kc = 0; kc < 8; kc++) {
            const int cur = kc & 1, nxt = cur ^ 1;
            CP_WAIT0();
            __syncthreads();
            float4 v4[4];
            if (kc < 7) {
                issueB1(kc + 1, nxt);
                const float* src = frow + (kc + 1) * 64 + aseg * 16;
                #pragma unroll
                for (int j = 0; j < 4; j++) v4[j] = *(const float4*)(src + j * 4);
            }
            mma_chunk_ldsm<ASTR, ASTR, 4>(acc,
                sb + (A_HI(cur) + wrow * 32 * ASTR) * 4 + laneA_A,
                sb + (A_LO(cur) + wrow * 32 * ASTR) * 4 + laneA_A,
                sb + (B1_HI(cur) + wcol * 64 * ASTR) * 4 + laneB_A,
                sb + (B1_LO(cur) + wcol * 64 * ASTR) * 4 + laneB_A);
            if (kc < 7) stageA(v4, nxt);
        }
    }
    __syncthreads();   // layer-1 MMA done: safe to write h (aliases B1) & B2 prologue (aliases A)

    issueB2(0, 0);     // layer-2 prologue overlaps epilogue 1

    // epilogue 1: relu + bias -> h
    #pragma unroll
    for (int mi = 0; mi < 2; mi++) {
        int r0 = wrow * 32 + mi * 16 + gid;
        #pragma unroll
        for (int ni = 0; ni < 8; ni++) {
            int col = wcol * 64 + ni * 8 + 2 * tig;
            int cp  = col >> 1;
            float v0 = fmaxf(acc[mi][ni][0] + sB1[col], 0.f);
            float v1 = fmaxf(acc[mi][ni][1] + sB1[col + 1], 0.f);
            float v2 = fmaxf(acc[mi][ni][2] + sB1[col], 0.f);
            float v3 = fmaxf(acc[mi][ni][3] + sB1[col + 1], 0.f);
            uint32_t hp, lp;
            split_pack(v0, v1, hp, lp);
            hHi[r0 * HSTR + cp] = hp; hLo[r0 * HSTR + cp] = lp;
            split_pack(v2, v3, hp, lp);
            hHi[(r0 + 8) * HSTR + cp] = hp; hLo[(r0 + 8) * HSTR + cp] = lp;
            acc[mi][ni][0] = 0.f; acc[mi][ni][1] = 0.f;
            acc[mi][ni][2] = 0.f; acc[mi][ni][3] = 0.f;
        }
    }

    // ============ Layer 2 pipeline: 8 chunks of K=32 ============
    #pragma unroll 1
    for (int kc = 0; kc < 8; kc++) {
        const int cur = kc & 1, nxt = cur ^ 1;
        CP_WAIT0();
        __syncthreads();
        if (kc < 7) issueB2(kc + 1, nxt);
        mma_chunk_ldsm<HSTR, B2STR, 2>(acc,
            sb + (OFF_HHI + wrow * 32 * HSTR + kc * 16) * 4 + laneA_H,
            sb + (OFF_HLO + wrow * 32 * HSTR + kc * 16) * 4 + laneA_H,
            sb + (B2_HI(cur) + wcol * 64 * B2STR) * 4 + laneB_B2,
            sb + (B2_LO(cur) + wcol * 64 * B2STR) * 4 + laneB_B2);
    }
    __syncthreads();   // layer-2 MMA done: safe to overwrite h and B2 region (W3)

    // stage W3T rows 0..7 (first 8 out cols), K=256
    if (t < 64) {
        int n = t >> 3, i = (t & 7) * 16;
        const uint4* sh = (const uint4*)(w3h + (size_t)n * H_DIM + i * 2);
        const uint4* sl = (const uint4*)(w3l + (size_t)n * H_DIM + i * 2);
        #pragma unroll
        for (int j = 0; j < 4; j++) {
            *(uint4*)&sm[OFF_W3HI + n * HSTR + i + j * 4] = sh[j];
            *(uint4*)&sm[OFF_W3LO + n * HSTR + i + j * 4] = sl[j];
        }
    }

    // epilogue 2: relu + bias -> h (overwrite)
    #pragma unroll
    for (int mi = 0; mi < 2; mi++) {
        int r0 = wrow * 32 + mi * 16 + gid;
        #pragma unroll
        for (int ni = 0; ni < 8; ni++) {
            int col = wcol * 64 + ni * 8 + 2 * tig;
            int cp  = col >> 1;
            float v0 = fmaxf(acc[mi][ni][0] + sB2[col], 0.f);
            float v1 = fmaxf(acc[mi][ni][1] + sB2[col + 1], 0.f);
            float v2 = fmaxf(acc[mi][ni][2] + sB2[col], 0.f);
            float v3 = fmaxf(acc[mi][ni][3] + sB2[col + 1], 0.f);
            uint32_t hp, lp;
            split_pack(v0, v1, hp, lp);
            hHi[r0 * HSTR + cp] = hp; hLo[r0 * HSTR + cp] = lp;
            split_pack(v2, v3, hp, lp);
            hHi[(r0 + 8) * HSTR + cp] = hp; hLo[(r0 + 8) * HSTR + cp] = lp;
        }
    }
    __syncthreads();

    // ============ Layer 3: y = h2 @ W3[:, :8] + b3 (warps 0..7) ============
    if (wid < 8) {
        float acc3[4] = {0.f, 0.f, 0.f, 0.f};
        const uint32_t* pAh = hHi + wid * 16 * HSTR;
        const uint32_t* pAl = hLo + wid * 16 * HSTR;
        const uint32_t* w3H = sm + OFF_W3HI;
        const uint32_t* w3L = sm + OFF_W3LO;
        #pragma unroll
        for (int ks = 0; ks < 16; ks++) {
            const int kb = ks * 8 + tig;
            uint32_t ah[4], al[4];
            ah[0] = pAh[gid * HSTR + kb];       ah[1] = pAh[(gid + 8) * HSTR + kb];
            ah[2] = pAh[gid * HSTR + kb + 4];   ah[3] = pAh[(gid + 8) * HSTR + kb + 4];
            al[0] = pAl[gid * HSTR + kb];       al[1] = pAl[(gid + 8) * HSTR + kb];
            al[2] = pAl[gid * HSTR + kb + 4];   al[3] = pAl[(gid + 8) * HSTR + kb + 4];
            uint32_t bh[2] = { w3H[gid * HSTR + kb], w3H[gid * HSTR + kb + 4] };
            uint32_t bl[2] = { w3L[gid * HSTR + kb], w3L[gid * HSTR + kb + 4] };
            mma16816(acc3, ah, bh);
            mma16816(acc3, ah, bl);
            mma16816(acc3, al, bh);
        }
        int r0 = wid * 16 + gid;
        int c  = 2 * tig;
        if (r0 < nrows) {
            float* o = out + (size_t)sIdx[r0] * DA + c;
            o[0] = acc3[0] + sB3[c];
            o[1] = acc3[1] + sB3[c + 1];
        }
        if (r0 + 8 < nrows) {
            float* o = out + (size_t)sIdx[r0 + 8] * DA + c;
            o[0] = acc3[2] + sB3[c];
            o[1] = acc3[3] + sB3[c + 1];
        }
    }
}

extern "C" void kernel_launch(void* const* d_in, const int* in_sizes, int n_in,
                              void* d_out, int out_size)
{
    const float* features = (const float*)d_in[0];
    const float* W1 = (const float*)d_in[1];
    const float* b1 = (const float*)d_in[2];
    const float* W2 = (const float*)d_in[3];
    const float* b2 = (const float*)d_in[4];
    const float* W3 = (const float*)d_in[5];
    const float* b3 = (const float*)d_in[6];
    const int*   ma = (const int*)d_in[7];
    float* out = (float*)d_out;

    cudaFuncSetAttribute(moe_mma_kernel, cudaFuncAttributeMaxDynamicSharedMemorySize,
                         SMEM_WORDS * 4);

    zero_counts_kernel<<<1, 32>>>();
    scatter_kernel<<<B_ROWS / 256, 256>>>(ma);
    prep_weights<<<dim3(128, E_NUM, 3), dim3(32, 8)>>>(W1, W2, W3);
    moe_mma_kernel<<<dim3(NTILES, E_NUM), 512, SMEM_WORDS * 4>>>(features, b1, b2, b3, out);
}

// round 9
// speedup vs baseline: 3.6773x; 1.0308x over previous
#include <cuda_runtime.h>
#include <cuda_bf16.h>
#include <cstdint>

#define B_ROWS 16384
#define F_DIM  512
#define H_DIM  256
#define E_NUM  8
#define OUT_DIM 32
#define DA     8
#define TM     128
#define NTILES (B_ROWS / TM)   // 128

#define ASTR 36    // b32 stride, 64-bf16 rows (32 words + 4 pad)
#define B2STR 20   // b32 stride, 32-bf16 rows (16 words + 4 pad)
#define HSTR 132   // b32 stride, 256-bf16 h rows (128 words + 4 pad)

// ---------------- device scratch ----------------
__device__ int g_counts[E_NUM];
__device__ int g_bucket[E_NUM][B_ROWS];

__device__ __align__(16) __nv_bfloat16 g_W1T_hi[E_NUM][H_DIM][F_DIM];
__device__ __align__(16) __nv_bfloat16 g_W1T_lo[E_NUM][H_DIM][F_DIM];
__device__ __align__(16) __nv_bfloat16 g_W2T_hi[E_NUM][H_DIM][H_DIM];
__device__ __align__(16) __nv_bfloat16 g_W2T_lo[E_NUM][H_DIM][H_DIM];
__device__ __align__(16) __nv_bfloat16 g_W3T_hi[E_NUM][OUT_DIM][H_DIM];
__device__ __align__(16) __nv_bfloat16 g_W3T_lo[E_NUM][OUT_DIM][H_DIM];

__device__ __forceinline__ void split1(float x, __nv_bfloat16& h, __nv_bfloat16& l) {
    h = __float2bfloat16_rn(x);
    l = __float2bfloat16_rn(x - __bfloat162float(h));
}
__device__ __forceinline__ uint32_t packbf(__nv_bfloat16 a, __nv_bfloat16 b) {
    __nv_bfloat162 t(a, b);
    return *reinterpret_cast<uint32_t*>(&t);
}
__device__ __forceinline__ void split_pack(float v0, float v1, uint32_t& hp, uint32_t& lp) {
    __nv_bfloat16 h0, l0, h1, l1;
    split1(v0, h0, l0); split1(v1, h1, l1);
    hp = packbf(h0, h1);
    lp = packbf(l0, l1);
}
__device__ __forceinline__ uint32_t smem_u32(const void* p) {
    uint32_t a;
    asm("{ .reg .u64 t; cvta.to.shared.u64 t, %1; cvt.u32.u64 %0, t; }" : "=r"(a) : "l"(p));
    return a;
}
__device__ __forceinline__ void cpasync16(uint32_t dst, const void* src) {
    asm volatile("cp.async.cg.shared.global [%0], [%1], 16;" :: "r"(dst), "l"(src));
}
#define CP_COMMIT() asm volatile("cp.async.commit_group;")
#define CP_WAIT0()  asm volatile("cp.async.wait_group 0;")

__device__ __forceinline__ void mma16816(float* d, const uint32_t* a, const uint32_t* b) {
    asm volatile("mma.sync.aligned.m16n8k16.row.col.f32.bf16.bf16.f32 "
        "{%0,%1,%2,%3}, {%4,%5,%6,%7}, {%8,%9}, {%0,%1,%2,%3};"
        : "+f"(d[0]), "+f"(d[1]), "+f"(d[2]), "+f"(d[3])
        : "r"(a[0]), "r"(a[1]), "r"(a[2]), "r"(a[3]), "r"(b[0]), "r"(b[1]));
}
__device__ __forceinline__ void ldsm_x4(uint32_t* r, uint32_t addr) {
    asm volatile("ldmatrix.sync.aligned.m8n8.x4.shared.b16 {%0,%1,%2,%3}, [%4];"
        : "=r"(r[0]), "=r"(r[1]), "=r"(r[2]), "=r"(r[3]) : "r"(addr));
}

// Warp-tile (16 rows x 64 cols) over NKS*16 K, bf16x3 split, ldmatrix frags.
template<int LDA, int LDB, int NKS>
__device__ __forceinline__ void mma_chunk_ldsm(
    float acc[8][4],
    uint32_t aHi, uint32_t aLo, uint32_t bHi, uint32_t bLo)
{
    #pragma unroll
    for (int ks = 0; ks < NKS; ks++) {
        uint32_t ah[4], al[4];
        ldsm_x4(ah, aHi + ks * 32);
        ldsm_x4(al, aLo + ks * 32);
        #pragma unroll
        for (int p = 0; p < 4; p++) {
            uint32_t bh[4], bl[4];
            ldsm_x4(bh, bHi + p * (16 * LDB * 4) + ks * 32);
            ldsm_x4(bl, bLo + p * (16 * LDB * 4) + ks * 32);
            #pragma unroll
            for (int q = 0; q < 2; q++) {
                const int ni = p * 2 + q;
                mma16816(acc[ni], ah, bh + q * 2);
                mma16816(acc[ni], ah, bl + q * 2);
                mma16816(acc[ni], al, bh + q * 2);
            }
        }
    }
}

// ---------------- prep kernels ----------------
__global__ void zero_counts_kernel() {
    if (threadIdx.x < E_NUM) g_counts[threadIdx.x] = 0;
}
__global__ void scatter_kernel(const int* __restrict__ ma) {
    int i = blockIdx.x * blockDim.x + threadIdx.x;
    if (i < B_ROWS) {
        int e = ma[i];
        int p = atomicAdd(&g_counts[e], 1);
        g_bucket[e][p] = i;
    }
}
__global__ void prep_weights(const float* __restrict__ W1,
                             const float* __restrict__ W2,
                             const float* __restrict__ W3) {
    int z = blockIdx.z, e = blockIdx.y;
    int Kd = (z == 0) ? F_DIM : H_DIM;
    int Nd = (z == 0) ? H_DIM : ((z == 1) ? H_DIM : OUT_DIM);
    int ntn = Nd / 32;
    int tk = (blockIdx.x / ntn) * 32;
    int tn = (blockIdx.x % ntn) * 32;
    if (tk >= Kd) return;
    const float* src = ((z == 0) ? W1 : (z == 1) ? W2 : W3) + (size_t)e * Kd * Nd;
    __nv_bfloat16* dh = (z == 0) ? &g_W1T_hi[e][0][0] : (z == 1) ? &g_W2T_hi[e][0][0] : &g_W3T_hi[e][0][0];
    __nv_bfloat16* dl = (z == 0) ? &g_W1T_lo[e][0][0] : (z == 1) ? &g_W2T_lo[e][0][0] : &g_W3T_lo[e][0][0];
    __shared__ float tile[32][33];
    int tx = threadIdx.x, ty = threadIdx.y;   // 32 x 8
    #pragma unroll
    for (int r = 0; r < 4; r++)
        tile[ty + r * 8][tx] = src[(size_t)(tk + ty + r * 8) * Nd + tn + tx];
    __syncthreads();
    #pragma unroll
    for (int r = 0; r < 4; r++) {
        int n = tn + ty + r * 8, k = tk + tx;
        float v = tile[tx][ty + r * 8];
        __nv_bfloat16 h, l; split1(v, h, l);
        dh[(size_t)n * Kd + k] = h;
        dl[(size_t)n * Kd + k] = l;
    }
}

// ---------------- smem layout (b32 words) ----------------
#define B1_HI(b) ((b) * 18432)
#define B1_LO(b) (B1_HI(b) + 9216)
#define A_HI(b)  (36864 + (b) * 9216)
#define A_LO(b)  (A_HI(b) + 4608)
#define OFF_HHI  0
#define OFF_HLO  16896
#define B2_HI(b) (36864 + (b) * 10240)
#define B2_LO(b) (B2_HI(b) + 5120)
#define OFF_W3HI 36864
#define OFF_W3LO (36864 + 1056)
#define OFF_IDX  57344
#define OFF_SB1  57472
#define OFF_SB2  57728
#define OFF_SB3  57984
#define SMEM_WORDS 57992     // 231968 bytes

// ---------------- main MMA kernel: 1024 threads, 8x4 warps ----------------
__global__ __launch_bounds__(1024, 1)
void moe_mma_kernel(const float* __restrict__ features,
                    const float* __restrict__ b1,
                    const float* __restrict__ b2,
                    const float* __restrict__ b3,
                    float* __restrict__ out)
{
    const int e = blockIdx.y;
    const int count = g_counts[e];
    const int row0 = blockIdx.x * TM;
    if (row0 >= count) return;
    const int nrows = min(TM, count - row0);

    extern __shared__ uint32_t sm[];
    const uint32_t sb = smem_u32(sm);
    int*   sIdx = (int*)(sm + OFF_IDX);
    float* sB1  = (float*)(sm + OFF_SB1);
    float* sB2  = (float*)(sm + OFF_SB2);
    float* sB3  = (float*)(sm + OFF_SB3);
    uint32_t* hHi = sm + OFF_HHI;
    uint32_t* hLo = sm + OFF_HLO;

    const int t    = threadIdx.x;
    const int wid  = t >> 5;
    const int lane = t & 31;
    const int gid  = lane >> 2;
    const int tig  = lane & 3;
    const int wrow = wid & 7;       // 8 row-warps * 16 rows
    const int wcol = wid >> 3;      // 4 col-warps * 64 cols

    // ldmatrix per-lane byte offsets (x4 = 16 rows x 16 bytes)
    const int l8 = lane & 7, lq = lane >> 3;
    const int laneA_A  = ((l8 + 8 * (lq & 1)) * ASTR)  * 4 + (lq >> 1) * 16;
    const int laneA_H  = ((l8 + 8 * (lq & 1)) * HSTR)  * 4 + (lq >> 1) * 16;
    const int laneB_A  = ((l8 + 8 * (lq >> 1)) * ASTR) * 4 + (lq & 1) * 16;
    const int laneB_B2 = ((l8 + 8 * (lq >> 1)) * B2STR) * 4 + (lq & 1) * 16;

    if (t < TM) sIdx[t] = g_bucket[e][row0 + min(t, nrows - 1)];
    if (t < H_DIM) {
        sB1[t] = b1[e * H_DIM + t];
        sB2[t] = b2[e * H_DIM + t];
    }
    if (t < DA) sB3[t] = b3[e * OUT_DIM + t];
    __syncthreads();

    // staging roles (1024 threads)
    const int arow = t >> 3, aseg = t & 7;     // A: 128 rows x 8 segs of 8 floats
    const int brow = t >> 2, bq = t & 3;       // B: 256 rows x 4 quarters
    const float* frow = features + (size_t)sIdx[arow] * F_DIM;

    const __nv_bfloat16* w1h = &g_W1T_hi[e][0][0];
    const __nv_bfloat16* w1l = &g_W1T_lo[e][0][0];
    const __nv_bfloat16* w2h = &g_W2T_hi[e][0][0];
    const __nv_bfloat16* w2l = &g_W2T_lo[e][0][0];
    const __nv_bfloat16* w3h = &g_W3T_hi[e][0][0];
    const __nv_bfloat16* w3l = &g_W3T_lo[e][0][0];

    float acc[8][4];
    #pragma unroll
    for (int ni = 0; ni < 8; ni++)
        #pragma unroll
        for (int c = 0; c < 4; c++) acc[ni][c] = 0.f;

    auto issueB1 = [&](int kc, int buf) {
        const __nv_bfloat16* sh = w1h + (size_t)brow * F_DIM + kc * 64 + bq * 16;
        const __nv_bfloat16* sl = w1l + (size_t)brow * F_DIM + kc * 64 + bq * 16;
        uint32_t dh = sb + (B1_HI(buf) + brow * ASTR + bq * 8) * 4;
        uint32_t dl = sb + (B1_LO(buf) + brow * ASTR + bq * 8) * 4;
        #pragma unroll
        for (int c = 0; c < 2; c++) {
            cpasync16(dh + c * 16, sh + c * 8);
            cpasync16(dl + c * 16, sl + c * 8);
        }
        CP_COMMIT();
    };
    auto stageA = [&](const float4* v4, int buf) {
        uint32_t* dH = sm + A_HI(buf) + arow * ASTR + aseg * 4;
        uint32_t* dL = sm + A_LO(buf) + arow * ASTR + aseg * 4;
        #pragma unroll
        for (int j = 0; j < 2; j++) {
            uint32_t h0, l0, h1, l1;
            split_pack(v4[j].x, v4[j].y, h0, l0);
            split_pack(v4[j].z, v4[j].w, h1, l1);
            dH[j * 2] = h0; dH[j * 2 + 1] = h1;
            dL[j * 2] = l0; dL[j * 2 + 1] = l1;
        }
    };
    auto issueB2 = [&](int kc, int buf) {
        const __nv_bfloat16* sh = w2h + (size_t)brow * H_DIM + kc * 32 + bq * 8;
        const __nv_bfloat16* sl = w2l + (size_t)brow * H_DIM + kc * 32 + bq * 8;
        uint32_t dh = sb + (B2_HI(buf) + brow * B2STR + bq * 4) * 4;
        uint32_t dl = sb + (B2_LO(buf) + brow * B2STR + bq * 4) * 4;
        cpasync16(dh, sh);
        cpasync16(dl, sl);
        CP_COMMIT();
    };

    // ============ Layer 1 pipeline: 8 chunks of K=64 ============
    {
        issueB1(0, 0);
        {
            float4 v4[2];
            const float* src = frow + aseg * 8;
            v4[0] = *(const float4*)(src);
            v4[1] = *(const float4*)(src + 4);
            stageA(v4, 0);
        }
        #pragma unroll 1
        for (int kc = 0; kc < 8; kc++) {
            const int cur = kc & 1, nxt = cur ^ 1;
            CP_WAIT0();
            __syncthreads();
            float4 v4[2];
            if (kc < 7) {
                issueB1(kc + 1, nxt);
                const float* src = frow + (kc + 1) * 64 + aseg * 8;
                v4[0] = *(const float4*)(src);
                v4[1] = *(const float4*)(src + 4);
            }
            mma_chunk_ldsm<ASTR, ASTR, 4>(acc,
                sb + (A_HI(cur) + wrow * 16 * ASTR) * 4 + laneA_A,
                sb + (A_LO(cur) + wrow * 16 * ASTR) * 4 + laneA_A,
                sb + (B1_HI(cur) + wcol * 64 * ASTR) * 4 + laneB_A,
                sb + (B1_LO(cur) + wcol * 64 * ASTR) * 4 + laneB_A);
            if (kc < 7) stageA(v4, nxt);
        }
    }
    __syncthreads();   // layer-1 MMA done: safe to write h (aliases B1) & B2 prologue (aliases A)

    issueB2(0, 0);     // layer-2 prologue overlaps epilogue 1

    // epilogue 1: relu + bias -> h
    {
        int r0 = wrow * 16 + gid;
        #pragma unroll
        for (int ni = 0; ni < 8; ni++) {
            int col = wcol * 64 + ni * 8 + 2 * tig;
            int cp  = col >> 1;
            float v0 = fmaxf(acc[ni][0] + sB1[col], 0.f);
            float v1 = fmaxf(acc[ni][1] + sB1[col + 1], 0.f);
            float v2 = fmaxf(acc[ni][2] + sB1[col], 0.f);
            float v3 = fmaxf(acc[ni][3] + sB1[col + 1], 0.f);
            uint32_t hp, lp;
            split_pack(v0, v1, hp, lp);
            hHi[r0 * HSTR + cp] = hp; hLo[r0 * HSTR + cp] = lp;
            split_pack(v2, v3, hp, lp);
            hHi[(r0 + 8) * HSTR + cp] = hp; hLo[(r0 + 8) * HSTR + cp] = lp;
            acc[ni][0] = 0.f; acc[ni][1] = 0.f;
            acc[ni][2] = 0.f; acc[ni][3] = 0.f;
        }
    }

    // ============ Layer 2 pipeline: 8 chunks of K=32 ============
    #pragma unroll 1
    for (int kc = 0; kc < 8; kc++) {
        const int cur = kc & 1, nxt = cur ^ 1;
        CP_WAIT0();
        __syncthreads();
        if (kc < 7) issueB2(kc + 1, nxt);
        mma_chunk_ldsm<HSTR, B2STR, 2>(acc,
            sb + (OFF_HHI + wrow * 16 * HSTR + kc * 16) * 4 + laneA_H,
            sb + (OFF_HLO + wrow * 16 * HSTR + kc * 16) * 4 + laneA_H,
            sb + (B2_HI(cur) + wcol * 64 * B2STR) * 4 + laneB_B2,
            sb + (B2_LO(cur) + wcol * 64 * B2STR) * 4 + laneB_B2);
    }
    __syncthreads();   // layer-2 MMA done: safe to overwrite h and B2 region (W3)

    // stage W3T rows 0..7 (first 8 out cols), K=256
    if (t < 64) {
        int n = t >> 3, i = (t & 7) * 16;
        const uint4* sh = (const uint4*)(w3h + (size_t)n * H_DIM + i * 2);
        const uint4* sl = (const uint4*)(w3l + (size_t)n * H_DIM + i * 2);
        #pragma unroll
        for (int j = 0; j < 4; j++) {
            *(uint4*)&sm[OFF_W3HI + n * HSTR + i + j * 4] = sh[j];
            *(uint4*)&sm[OFF_W3LO + n * HSTR + i + j * 4] = sl[j];
        }
    }

    // epilogue 2: relu + bias -> h (overwrite)
    {
        int r0 = wrow * 16 + gid;
        #pragma unroll
        for (int ni = 0; ni < 8; ni++) {
            int col = wcol * 64 + ni * 8 + 2 * tig;
            int cp  = col >> 1;
            float v0 = fmaxf(acc[ni][0] + sB2[col], 0.f);
            float v1 = fmaxf(acc[ni][1] + sB2[col + 1], 0.f);
            float v2 = fmaxf(acc[ni][2] + sB2[col], 0.f);
            float v3 = fmaxf(acc[ni][3] + sB2[col + 1], 0.f);
            uint32_t hp, lp;
            split_pack(v0, v1, hp, lp);
            hHi[r0 * HSTR + cp] = hp; hLo[r0 * HSTR + cp] = lp;
            split_pack(v2, v3, hp, lp);
            hHi[(r0 + 8) * HSTR + cp] = hp; hLo[(r0 + 8) * HSTR + cp] = lp;
        }
    }
    __syncthreads();

    // ============ Layer 3: y = h2 @ W3[:, :8] + b3 (warps 0..7) ============
    if (wid < 8) {
        float acc3[4] = {0.f, 0.f, 0.f, 0.f};
        const uint32_t* pAh = hHi + wid * 16 * HSTR;
        const uint32_t* pAl = hLo + wid * 16 * HSTR;
        const uint32_t* w3H = sm + OFF_W3HI;
        const uint32_t* w3L = sm + OFF_W3LO;
        #pragma unroll
        for (int ks = 0; ks < 16; ks++) {
            const int kb = ks * 8 + tig;
            uint32_t ah[4], al[4];
            ah[0] = pAh[gid * HSTR + kb];       ah[1] = pAh[(gid + 8) * HSTR + kb];
            ah[2] = pAh[gid * HSTR + kb + 4];   ah[3] = pAh[(gid + 8) * HSTR + kb + 4];
            al[0] = pAl[gid * HSTR + kb];       al[1] = pAl[(gid + 8) * HSTR + kb];
            al[2] = pAl[gid * HSTR + kb + 4];   al[3] = pAl[(gid + 8) * HSTR + kb + 4];
            uint32_t bh[2] = { w3H[gid * HSTR + kb], w3H[gid * HSTR + kb + 4] };
            uint32_t bl[2] = { w3L[gid * HSTR + kb], w3L[gid * HSTR + kb + 4] };
            mma16816(acc3, ah, bh);
            mma16816(acc3, ah, bl);
            mma16816(acc3, al, bh);
        }
        int r0 = wid * 16 + gid;
        int c  = 2 * tig;
        if (r0 < nrows) {
            float* o = out + (size_t)sIdx[r0] * DA + c;
            o[0] = acc3[0] + sB3[c];
            o[1] = acc3[1] + sB3[c + 1];
        }
        if (r0 + 8 < nrows) {
            float* o = out + (size_t)sIdx[r0 + 8] * DA + c;
            o[0] = acc3[2] + sB3[c];
            o[1] = acc3[3] + sB3[c + 1];
        }
    }
}

extern "C" void kernel_launch(void* const* d_in, const int* in_sizes, int n_in,
                              void* d_out, int out_size)
{
    const float* features = (const float*)d_in[0];
    const float* W1 = (const float*)d_in[1];
    const float* b1 = (const float*)d_in[2];
    const float* W2 = (const float*)d_in[3];
    const float* b2 = (const float*)d_in[4];
    const float* W3 = (const float*)d_in[5];
    const float* b3 = (const float*)d_in[6];
    const int*   ma = (const int*)d_in[7];
    float* out = (float*)d_out;

    cudaFuncSetAttribute(moe_mma_kernel, cudaFuncAttributeMaxDynamicSharedMemorySize,
                         SMEM_WORDS * 4);

    zero_counts_kernel<<<1, 32>>>();
    scatter_kernel<<<B_ROWS / 256, 256>>>(ma);
    prep_weights<<<dim3(128, E_NUM, 3), dim3(32, 8)>>>(W1, W2, W3);
    moe_mma_kernel<<<dim3(NTILES, E_NUM), 1024, SMEM_WORDS * 4>>>(features, b1, b2, b3, out);
}